// round 1
// baseline (speedup 1.0000x reference)
#include <cuda_runtime.h>
#include <math.h>

// Problem constants (fixed by setup_inputs)
#define D      128
#define NGRAPH 64
#define LROWS  2048

// Scratch: Gram matrices for all 64 graphs (4MB) + squared-transposed mp_w
__device__ float g_grams[NGRAPH * D * D];
__device__ float g_w2t[D * D];

// ---------------------------------------------------------------------------
// Zero the gram accumulators (must run every launch; atomic accumulation).
// ---------------------------------------------------------------------------
__global__ void zero_grams_kernel() {
    int idx = blockIdx.x * blockDim.x + threadIdx.x;
    float4* p = (float4*)g_grams;
    if (idx < (NGRAPH * D * D) / 4) p[idx] = make_float4(0.f, 0.f, 0.f, 0.f);
}

// ---------------------------------------------------------------------------
// w2t[d][p] = mp_w[p][d]^2  (transposed so main kernel stages coalesced)
// ---------------------------------------------------------------------------
__global__ void w2t_kernel(const float* __restrict__ mp_w) {
    int idx = blockIdx.x * blockDim.x + threadIdx.x;  // 0..16383
    int p = idx >> 7;
    int d = idx & (D - 1);
    float v = mp_w[idx];
    g_w2t[d * D + p] = v * v;
}

// ---------------------------------------------------------------------------
// Gram kernel: Gram[g] = X_g^T X_g, X_g is 2048x128.
// Split-K: 8 blocks per graph, each does 256 rows, atomicAdd-reduced.
// Block: 256 threads = 16x16 grid of 8x8 register tiles over the 128x128 out.
// ---------------------------------------------------------------------------
#define GSPLIT 8
#define GROWS  (LROWS / GSPLIT)   // 256

__global__ __launch_bounds__(256) void gram_kernel(const float* __restrict__ feats) {
    __shared__ float sX[32][D];

    int graph = blockIdx.x >> 3;
    int chunk = blockIdx.x & 7;
    const float* X = feats + ((size_t)graph * LROWS + (size_t)chunk * GROWS) * D;

    int tid = threadIdx.x;
    int ta8 = (tid >> 4) * 8;
    int tb8 = (tid & 15) * 8;

    float acc[8][8];
#pragma unroll
    for (int i = 0; i < 8; i++)
#pragma unroll
        for (int j = 0; j < 8; j++) acc[i][j] = 0.f;

    for (int k0 = 0; k0 < GROWS; k0 += 32) {
        // stage 32x128 rows (1024 float4, 4 per thread), coalesced
        const float4* src = (const float4*)(X + (size_t)k0 * D);
        float4* dst = (float4*)&sX[0][0];
#pragma unroll
        for (int q = 0; q < 4; q++) dst[tid + 256 * q] = src[tid + 256 * q];
        __syncthreads();

#pragma unroll 4
        for (int k = 0; k < 32; k++) {
            float av[8], bv[8];
            *(float4*)&av[0] = *(const float4*)&sX[k][ta8];
            *(float4*)&av[4] = *(const float4*)&sX[k][ta8 + 4];
            *(float4*)&bv[0] = *(const float4*)&sX[k][tb8];
            *(float4*)&bv[4] = *(const float4*)&sX[k][tb8 + 4];
#pragma unroll
            for (int i = 0; i < 8; i++)
#pragma unroll
                for (int j = 0; j < 8; j++)
                    acc[i][j] = fmaf(av[i], bv[j], acc[i][j]);
        }
        __syncthreads();
    }

    float* G = g_grams + (size_t)graph * D * D;
#pragma unroll
    for (int i = 0; i < 8; i++)
#pragma unroll
        for (int j = 0; j < 8; j++)
            atomicAdd(&G[(ta8 + i) * D + tb8 + j], acc[i][j]);
}

// ---------------------------------------------------------------------------
// Fused match kernel.
// Each block: 32 rows of one graph. 256 threads = 16(row-pairs) x 16(col-octs).
// Phase 1: Y = X @ Gram[gi^1]        (Gram is symmetric)
// Phase 2: num/n1/n2 accumulated together over d, sharing w2 operand loads:
//   out[r][p] = (x.y * w2_p) / max(sqrt((x.x*w2_p)*(y.y*w2_p)), 1e-8)
// Static smem = exactly 48KB -> no attribute needed, 2+ blocks/SM.
// ---------------------------------------------------------------------------
#define TR 32

__global__ __launch_bounds__(256) void match_kernel(const float* __restrict__ feats,
                                                    float* __restrict__ out) {
    __shared__ float sX[TR * D];     // 16KB
    __shared__ float sY[TR * D];     // 16KB
    __shared__ float sG[16 * D];     // 8KB (Gram k-chunk)
    __shared__ float sW[16 * D];     // 8KB (w2t k-chunk)

    int tid = threadIdx.x;
    int tr  = tid >> 4;              // 0..15
    int tc8 = (tid & 15) * 8;        // perspective octet base
    int r0  = blockIdx.x * TR;
    int gi  = r0 / LROWS;
    const float* gram = g_grams + (size_t)(gi ^ 1) * D * D;

    // stage X tile (32x128 = 1024 float4)
    {
        const float4* src = (const float4*)(feats + (size_t)r0 * D);
        float4* dst = (float4*)sX;
#pragma unroll
        for (int q = 0; q < 4; q++) dst[tid + 256 * q] = src[tid + 256 * q];
    }

    const int row0 = tr * 2, row1 = tr * 2 + 1;

    // ---------------- Phase 1: Y = X @ Gram ----------------
    float ya[8], yb[8];
#pragma unroll
    for (int j = 0; j < 8; j++) { ya[j] = 0.f; yb[j] = 0.f; }

    for (int kc = 0; kc < 8; kc++) {
        const float4* gsrc = (const float4*)(gram + kc * 16 * D);
        float4* gdst = (float4*)sG;
        gdst[tid]       = gsrc[tid];
        gdst[tid + 256] = gsrc[tid + 256];
        __syncthreads();   // also orders the sX stage on first iteration

#pragma unroll 4
        for (int k = 0; k < 16; k++) {
            int kg = kc * 16 + k;
            float x0 = sX[row0 * D + kg];
            float x1 = sX[row1 * D + kg];
            float gv[8];
            *(float4*)&gv[0] = *(const float4*)&sG[k * D + tc8];
            *(float4*)&gv[4] = *(const float4*)&sG[k * D + tc8 + 4];
#pragma unroll
            for (int j = 0; j < 8; j++) {
                ya[j] = fmaf(x0, gv[j], ya[j]);
                yb[j] = fmaf(x1, gv[j], yb[j]);
            }
        }
        __syncthreads();
    }

    // write Y tile
    *(float4*)&sY[row0 * D + tc8]     = make_float4(ya[0], ya[1], ya[2], ya[3]);
    *(float4*)&sY[row0 * D + tc8 + 4] = make_float4(ya[4], ya[5], ya[6], ya[7]);
    *(float4*)&sY[row1 * D + tc8]     = make_float4(yb[0], yb[1], yb[2], yb[3]);
    *(float4*)&sY[row1 * D + tc8 + 4] = make_float4(yb[4], yb[5], yb[6], yb[7]);

    // ---------------- Phase 2: triple-accumulator match GEMM ----------------
    float n0[8], n1a[8], b0a[8], b1a[8], c0a[8], c1a[8];
#pragma unroll
    for (int j = 0; j < 8; j++) {
        n0[j] = 0.f; n1a[j] = 0.f; b0a[j] = 0.f; b1a[j] = 0.f; c0a[j] = 0.f; c1a[j] = 0.f;
    }

    for (int kc = 0; kc < 8; kc++) {
        const float4* wsrc = (const float4*)(g_w2t + kc * 16 * D);
        float4* wdst = (float4*)sW;
        wdst[tid]       = wsrc[tid];
        wdst[tid + 256] = wsrc[tid + 256];
        __syncthreads();   // also orders the sY writes on first iteration

#pragma unroll 4
        for (int k = 0; k < 16; k++) {
            int kg = kc * 16 + k;
            float x0 = sX[row0 * D + kg];
            float y0 = sY[row0 * D + kg];
            float x1 = sX[row1 * D + kg];
            float y1 = sY[row1 * D + kg];
            float a0 = x0 * y0, bb0 = x0 * x0, cc0 = y0 * y0;
            float a1 = x1 * y1, bb1 = x1 * x1, cc1 = y1 * y1;
            float wv[8];
            *(float4*)&wv[0] = *(const float4*)&sW[k * D + tc8];
            *(float4*)&wv[4] = *(const float4*)&sW[k * D + tc8 + 4];
#pragma unroll
            for (int j = 0; j < 8; j++) {
                n0[j]  = fmaf(a0,  wv[j], n0[j]);
                b0a[j] = fmaf(bb0, wv[j], b0a[j]);
                c0a[j] = fmaf(cc0, wv[j], c0a[j]);
                n1a[j] = fmaf(a1,  wv[j], n1a[j]);
                b1a[j] = fmaf(bb1, wv[j], b1a[j]);
                c1a[j] = fmaf(cc1, wv[j], c1a[j]);
            }
        }
        __syncthreads();
    }

    // ---------------- Epilogue: num / max(sqrt(n1sq*n2sq), eps) ----------------
    float o0[8], o1[8];
#pragma unroll
    for (int j = 0; j < 8; j++) {
        float d0 = fmaxf(sqrtf(b0a[j] * c0a[j]), 1e-8f);
        float d1 = fmaxf(sqrtf(b1a[j] * c1a[j]), 1e-8f);
        o0[j] = n0[j] / d0;
        o1[j] = n1a[j] / d1;
    }

    float* orow0 = out + (size_t)(r0 + row0) * D + tc8;
    float* orow1 = out + (size_t)(r0 + row1) * D + tc8;
    *(float4*)(orow0)     = make_float4(o0[0], o0[1], o0[2], o0[3]);
    *(float4*)(orow0 + 4) = make_float4(o0[4], o0[5], o0[6], o0[7]);
    *(float4*)(orow1)     = make_float4(o1[0], o1[1], o1[2], o1[3]);
    *(float4*)(orow1 + 4) = make_float4(o1[4], o1[5], o1[6], o1[7]);
}

// ---------------------------------------------------------------------------
extern "C" void kernel_launch(void* const* d_in, const int* in_sizes, int n_in,
                              void* d_out, int out_size) {
    const float* feats = (const float*)d_in[0];
    const float* mp_w  = (const float*)d_in[1];
    float* out = (float*)d_out;

    int N = in_sizes[0] / D;   // 131072 rows

    zero_grams_kernel<<<(NGRAPH * D * D / 4 + 255) / 256, 256>>>();
    w2t_kernel<<<(D * D + 255) / 256, 256>>>(mp_w);
    gram_kernel<<<NGRAPH * GSPLIT, 256>>>(feats);
    match_kernel<<<N / TR, 256>>>(feats, out);
}

// round 2
// speedup vs baseline: 1.4294x; 1.4294x over previous
#include <cuda_runtime.h>
#include <math.h>
#include <stdint.h>

// Problem constants (fixed by setup_inputs)
#define D      128
#define NGRAPH 64
#define LROWS  2048
#define EPS    1e-8f

// Scratch: Gram matrices for all 64 graphs (4MB) + squared-transposed mp_w
__device__ float g_grams[NGRAPH * D * D];
__device__ float g_w2t[D * D];

// ---------------------------------------------------------------------------
// f32x2 packed-math helpers (Blackwell FFMA2 path — PTX fma.rn.f32x2)
// ---------------------------------------------------------------------------
__device__ __forceinline__ uint64_t dup2(float v) {
    uint64_t r;
    asm("mov.b64 %0, {%1, %2};" : "=l"(r) : "f"(v), "f"(v));
    return r;
}
__device__ __forceinline__ void unpack2(uint64_t p, float& lo, float& hi) {
    asm("mov.b64 {%0, %1}, %2;" : "=f"(lo), "=f"(hi) : "l"(p));
}
__device__ __forceinline__ void fma2(uint64_t& d, uint64_t a, uint64_t b) {
    asm("fma.rn.f32x2 %0, %1, %2, %0;" : "+l"(d) : "l"(a), "l"(b));
}

// ---------------------------------------------------------------------------
__global__ void zero_grams_kernel() {
    int idx = blockIdx.x * blockDim.x + threadIdx.x;
    float4* p = (float4*)g_grams;
    if (idx < (NGRAPH * D * D) / 4) p[idx] = make_float4(0.f, 0.f, 0.f, 0.f);
}

// w2t[d][p] = mp_w[p][d]^2
__global__ void w2t_kernel(const float* __restrict__ mp_w) {
    int idx = blockIdx.x * blockDim.x + threadIdx.x;  // 0..16383
    int p = idx >> 7;
    int d = idx & (D - 1);
    float v = mp_w[idx];
    g_w2t[d * D + p] = v * v;
}

// ---------------------------------------------------------------------------
// Gram kernel: Gram[g] = X_g^T X_g (X_g: 2048x128). Split-K 8-way, atomicAdd.
// 256 threads = 16(ta) x 16(tb); thread tile 8x8, f32x2 column-packed.
// Strided col/row chunks (4ta+64i / 4tb+64j) -> conflict-free vector LDS.
// ---------------------------------------------------------------------------
#define GSPLIT 8
#define GROWS  (LROWS / GSPLIT)   // 256

__global__ __launch_bounds__(256) void gram_kernel(const float* __restrict__ feats) {
    __shared__ float sX[32 * D];

    int graph = blockIdx.x >> 3;
    int chunk = blockIdx.x & 7;
    const float* Xg = feats + ((size_t)graph * LROWS + (size_t)chunk * GROWS) * D;

    int tid = threadIdx.x;
    int ta = tid >> 4;      // 0..15 -> rows 4ta+c, 64+4ta+c
    int tb = tid & 15;      // 0..15 -> cols 4tb+c, 64+4tb+c

    uint64_t acc[8][4];     // [row r][col-pair]
#pragma unroll
    for (int r = 0; r < 8; r++)
#pragma unroll
        for (int p = 0; p < 4; p++) acc[r][p] = 0ull;

    for (int k0 = 0; k0 < GROWS; k0 += 32) {
        const float4* src = (const float4*)(Xg + (size_t)k0 * D);
        float4* dst = (float4*)sX;
#pragma unroll
        for (int q = 0; q < 4; q++) dst[tid + 256 * q] = src[tid + 256 * q];
        __syncthreads();

#pragma unroll 8
        for (int k = 0; k < 32; k++) {
            const float* row = sX + k * D;
            float4 A0 = *(const float4*)(row + 4 * ta);
            float4 A1 = *(const float4*)(row + 64 + 4 * ta);
            ulonglong2 B0 = *(const ulonglong2*)(row + 4 * tb);
            ulonglong2 B1 = *(const ulonglong2*)(row + 64 + 4 * tb);
            uint64_t da[8];
            da[0] = dup2(A0.x); da[1] = dup2(A0.y); da[2] = dup2(A0.z); da[3] = dup2(A0.w);
            da[4] = dup2(A1.x); da[5] = dup2(A1.y); da[6] = dup2(A1.z); da[7] = dup2(A1.w);
#pragma unroll
            for (int r = 0; r < 8; r++) {
                fma2(acc[r][0], da[r], B0.x);
                fma2(acc[r][1], da[r], B0.y);
                fma2(acc[r][2], da[r], B1.x);
                fma2(acc[r][3], da[r], B1.y);
            }
        }
        __syncthreads();
    }

    float* G = g_grams + (size_t)graph * D * D;
#pragma unroll
    for (int i = 0; i < 2; i++) {
#pragma unroll
        for (int c = 0; c < 4; c++) {
            int r = i * 4 + c;
            int grow = 64 * i + 4 * ta + c;
#pragma unroll
            for (int j = 0; j < 2; j++) {
                float f0, f1, f2, f3;
                unpack2(acc[r][2 * j], f0, f1);
                unpack2(acc[r][2 * j + 1], f2, f3);
                float* gp = G + grow * D + 64 * j + 4 * tb;
                atomicAdd(gp + 0, f0);
                atomicAdd(gp + 1, f1);
                atomicAdd(gp + 2, f2);
                atomicAdd(gp + 3, f3);
            }
        }
    }
}

// ---------------------------------------------------------------------------
// Fused match kernel, f32x2 packed.
// 128 threads = 16(row-pairs tr) x 8(col-threads tc); thread tile 2 rows x 16
// cols, cols owned as 4 strided float4 chunks: C(i) = 32*i + 4*tc.
// sX/sY padded to stride 132 floats -> warp's 4 scalar rows hit distinct banks.
// sB is shared between Gram chunks (phase 1) and w2t chunks (phase 2).
// Phase 1: Y = X @ Gram[gi^1]
// Phase 2: out[r][p] = (x.y*w2_p) / max(sqrt((x.x*w2_p)*(y.y*w2_p)), eps)
// ---------------------------------------------------------------------------
#define TR  32
#define SXS 132    // padded row stride in floats (132*4B, 16B-aligned)

__global__ __launch_bounds__(128) void match_kernel(const float* __restrict__ feats,
                                                    float* __restrict__ out) {
    __shared__ float sX[TR * SXS];   // 16.5KB
    __shared__ float sY[TR * SXS];   // 16.5KB
    __shared__ float sB[16 * D];     // 8KB (Gram chunk, then w2t chunk)

    int tid = threadIdx.x;
    int tr  = tid >> 3;              // 0..15 row-pair
    int tc  = tid & 7;               // 0..7 col-thread
    int r0  = blockIdx.x * TR;
    int gi  = r0 >> 11;              // /LROWS
    const float* gram = g_grams + (size_t)(gi ^ 1) * D * D;

    int row0 = tr * 2, row1 = row0 + 1;
    const float* pX0 = sX + row0 * SXS;
    const float* pX1 = sX + row1 * SXS;
    const float* pY0 = sY + row0 * SXS;
    const float* pY1 = sY + row1 * SXS;

    // stage X tile (32x128, padded stride): 1024 float4, 8 per thread
    {
        const float4* src = (const float4*)(feats + (size_t)r0 * D);
        float4* dst = (float4*)sX;
#pragma unroll
        for (int q = 0; q < 8; q++) {
            int idx = tid + 128 * q;
            int row = idx >> 5, kg = idx & 31;
            dst[row * (SXS / 4) + kg] = src[idx];
        }
    }

    // ---------------- Phase 1: Y = X @ Gram ----------------
    uint64_t ya[8], yb[8];
#pragma unroll
    for (int j = 0; j < 8; j++) { ya[j] = 0ull; yb[j] = 0ull; }

    for (int kc = 0; kc < 8; kc++) {
        const float4* gsrc = (const float4*)(gram + kc * 16 * D);
        float4* gdst = (float4*)sB;
#pragma unroll
        for (int q = 0; q < 4; q++) gdst[tid + 128 * q] = gsrc[tid + 128 * q];
        __syncthreads();   // also orders sX staging on first iteration

#pragma unroll 4
        for (int k = 0; k < 16; k++) {
            int kg = kc * 16 + k;
            uint64_t x00 = dup2(pX0[kg]);
            uint64_t x11 = dup2(pX1[kg]);
            const float* wrow = sB + k * D + 4 * tc;
#pragma unroll
            for (int i = 0; i < 4; i++) {
                ulonglong2 gv = *(const ulonglong2*)(wrow + 32 * i);
                fma2(ya[2 * i],     x00, gv.x);
                fma2(ya[2 * i + 1], x00, gv.y);
                fma2(yb[2 * i],     x11, gv.x);
                fma2(yb[2 * i + 1], x11, gv.y);
            }
        }
        __syncthreads();
    }

    // write Y tile (own rows, own strided col chunks)
#pragma unroll
    for (int i = 0; i < 4; i++) {
        float f0, f1, f2, f3;
        unpack2(ya[2 * i], f0, f1); unpack2(ya[2 * i + 1], f2, f3);
        *(float4*)(sY + row0 * SXS + 32 * i + 4 * tc) = make_float4(f0, f1, f2, f3);
        unpack2(yb[2 * i], f0, f1); unpack2(yb[2 * i + 1], f2, f3);
        *(float4*)(sY + row1 * SXS + 32 * i + 4 * tc) = make_float4(f0, f1, f2, f3);
    }

    // ---------------- Phase 2: triple-accumulator match ----------------
    uint64_t n0[8], b0[8], c0[8], n1[8], b1[8], c1[8];
#pragma unroll
    for (int j = 0; j < 8; j++) {
        n0[j] = 0ull; b0[j] = 0ull; c0[j] = 0ull;
        n1[j] = 0ull; b1[j] = 0ull; c1[j] = 0ull;
    }

    for (int kc = 0; kc < 8; kc++) {
        const float4* wsrc = (const float4*)(g_w2t + kc * 16 * D);
        float4* wdst = (float4*)sB;
#pragma unroll
        for (int q = 0; q < 4; q++) wdst[tid + 128 * q] = wsrc[tid + 128 * q];
        __syncthreads();   // also orders sY writes on first iteration

#pragma unroll 4
        for (int k = 0; k < 16; k++) {
            int kg = kc * 16 + k;
            float x0 = pX0[kg], y0 = pY0[kg];
            float x1 = pX1[kg], y1 = pY1[kg];
            uint64_t a0 = dup2(x0 * y0), bb0 = dup2(x0 * x0), cc0 = dup2(y0 * y0);
            uint64_t a1 = dup2(x1 * y1), bb1 = dup2(x1 * x1), cc1 = dup2(y1 * y1);
            const float* wrow = sB + k * D + 4 * tc;
#pragma unroll
            for (int i = 0; i < 4; i++) {
                ulonglong2 wv = *(const ulonglong2*)(wrow + 32 * i);
                fma2(n0[2 * i],     a0,  wv.x);
                fma2(n0[2 * i + 1], a0,  wv.y);
                fma2(b0[2 * i],     bb0, wv.x);
                fma2(b0[2 * i + 1], bb0, wv.y);
                fma2(c0[2 * i],     cc0, wv.x);
                fma2(c0[2 * i + 1], cc0, wv.y);
                fma2(n1[2 * i],     a1,  wv.x);
                fma2(n1[2 * i + 1], a1,  wv.y);
                fma2(b1[2 * i],     bb1, wv.x);
                fma2(b1[2 * i + 1], bb1, wv.y);
                fma2(c1[2 * i],     cc1, wv.x);
                fma2(c1[2 * i + 1], cc1, wv.y);
            }
        }
        __syncthreads();
    }

    // ---------------- Epilogue ----------------
    float* orow0 = out + (size_t)(r0 + row0) * D;
    float* orow1 = out + (size_t)(r0 + row1) * D;
#pragma unroll
    for (int i = 0; i < 4; i++) {
        float nu0, nu1, nu2, nu3, q0, q1, q2, q3, s0, s1, s2, s3;

        unpack2(n0[2 * i], nu0, nu1); unpack2(n0[2 * i + 1], nu2, nu3);
        unpack2(b0[2 * i], q0, q1);   unpack2(b0[2 * i + 1], q2, q3);
        unpack2(c0[2 * i], s0, s1);   unpack2(c0[2 * i + 1], s2, s3);
        float4 o;
        o.x = nu0 / fmaxf(sqrtf(q0 * s0), EPS);
        o.y = nu1 / fmaxf(sqrtf(q1 * s1), EPS);
        o.z = nu2 / fmaxf(sqrtf(q2 * s2), EPS);
        o.w = nu3 / fmaxf(sqrtf(q3 * s3), EPS);
        *(float4*)(orow0 + 32 * i + 4 * tc) = o;

        unpack2(n1[2 * i], nu0, nu1); unpack2(n1[2 * i + 1], nu2, nu3);
        unpack2(b1[2 * i], q0, q1);   unpack2(b1[2 * i + 1], q2, q3);
        unpack2(c1[2 * i], s0, s1);   unpack2(c1[2 * i + 1], s2, s3);
        o.x = nu0 / fmaxf(sqrtf(q0 * s0), EPS);
        o.y = nu1 / fmaxf(sqrtf(q1 * s1), EPS);
        o.z = nu2 / fmaxf(sqrtf(q2 * s2), EPS);
        o.w = nu3 / fmaxf(sqrtf(q3 * s3), EPS);
        *(float4*)(orow1 + 32 * i + 4 * tc) = o;
    }
}

// ---------------------------------------------------------------------------
extern "C" void kernel_launch(void* const* d_in, const int* in_sizes, int n_in,
                              void* d_out, int out_size) {
    const float* feats = (const float*)d_in[0];
    const float* mp_w  = (const float*)d_in[1];
    float* out = (float*)d_out;

    int N = in_sizes[0] / D;   // 131072 rows

    zero_grams_kernel<<<(NGRAPH * D * D / 4 + 255) / 256, 256>>>();
    w2t_kernel<<<(D * D + 255) / 256, 256>>>(mp_w);
    gram_kernel<<<NGRAPH * GSPLIT, 256>>>(feats);
    match_kernel<<<N / TR, 128>>>(feats, out);
}

// round 4
// speedup vs baseline: 2.5687x; 1.7971x over previous
#include <cuda_runtime.h>
#include <cuda_bf16.h>
#include <math.h>
#include <stdint.h>

#define D      128
#define NGRAPH 64
#define LROWS  2048
#define EPS    1e-8f

// ---------------------------------------------------------------------------
// Global scratch
// ---------------------------------------------------------------------------
__device__ float         g_grams[NGRAPH * D * D];
__device__ __nv_bfloat16 g_gh[NGRAPH * D * D];
__device__ __nv_bfloat16 g_gl[NGRAPH * D * D];
__device__ __nv_bfloat16 g_wh[D * D];
__device__ __nv_bfloat16 g_wl[D * D];

// ---------------------------------------------------------------------------
// Helpers
// ---------------------------------------------------------------------------
__device__ __forceinline__ uint32_t smem_to_u32(const void* p) {
    uint32_t a;
    asm("{ .reg .u64 t; cvta.to.shared.u64 t, %1; cvt.u32.u64 %0, t; }" : "=r"(a) : "l"(p));
    return a;
}

// pack two fp32 -> bf16x2 (lo in low half)
__device__ __forceinline__ uint32_t pack_bf2(float lo, float hi) {
    uint32_t r;
    asm("cvt.rn.bf16x2.f32 %0, %1, %2;" : "=r"(r) : "f"(hi), "f"(lo));
    return r;
}
__device__ __forceinline__ float bfu_lo(uint32_t u) { return __uint_as_float(u << 16); }
__device__ __forceinline__ float bfu_hi(uint32_t u) { return __uint_as_float(u & 0xFFFF0000u); }

__device__ __forceinline__ void ldsm4(uint32_t* r, uint32_t addr) {
    asm volatile("ldmatrix.sync.aligned.m8n8.x4.shared.b16 {%0,%1,%2,%3}, [%4];"
        : "=r"(r[0]), "=r"(r[1]), "=r"(r[2]), "=r"(r[3]) : "r"(addr));
}
__device__ __forceinline__ void ldsm2(uint32_t* r, uint32_t addr) {
    asm volatile("ldmatrix.sync.aligned.m8n8.x2.shared.b16 {%0,%1}, [%2];"
        : "=r"(r[0]), "=r"(r[1]) : "r"(addr));
}
__device__ __forceinline__ void mma16816(float* c, const uint32_t* a, const uint32_t* b) {
    asm volatile("mma.sync.aligned.m16n8k16.row.col.f32.bf16.bf16.f32 "
        "{%0,%1,%2,%3}, {%4,%5,%6,%7}, {%8,%9}, {%0,%1,%2,%3};"
        : "+f"(c[0]), "+f"(c[1]), "+f"(c[2]), "+f"(c[3])
        : "r"(a[0]), "r"(a[1]), "r"(a[2]), "r"(a[3]), "r"(b[0]), "r"(b[1]));
}

// f32x2 helpers for SIMT gram
__device__ __forceinline__ uint64_t dup2(float v) {
    uint64_t r;
    asm("mov.b64 %0, {%1, %2};" : "=l"(r) : "f"(v), "f"(v));
    return r;
}
__device__ __forceinline__ void unpack2(uint64_t p, float& lo, float& hi) {
    asm("mov.b64 {%0, %1}, %2;" : "=f"(lo), "=f"(hi) : "l"(p));
}
__device__ __forceinline__ void fma2(uint64_t& d, uint64_t a, uint64_t b) {
    asm("fma.rn.f32x2 %0, %1, %2, %0;" : "+l"(d) : "l"(a), "l"(b));
}

// ---------------------------------------------------------------------------
__global__ void zero_grams_kernel() {
    int idx = blockIdx.x * blockDim.x + threadIdx.x;
    float4* p = (float4*)g_grams;
    if (idx < (NGRAPH * D * D) / 4) p[idx] = make_float4(0.f, 0.f, 0.f, 0.f);
}

__global__ void wcvt_kernel(const float* __restrict__ mp_w) {
    int idx = blockIdx.x * blockDim.x + threadIdx.x;
    if (idx >= D * D) return;
    float v = mp_w[idx];
    float w2 = v * v;
    __nv_bfloat16 h = __float2bfloat16_rn(w2);
    g_wh[idx] = h;
    g_wl[idx] = __float2bfloat16_rn(w2 - __bfloat162float(h));
}

__global__ void gram_cvt_kernel() {
    int idx = blockIdx.x * blockDim.x + threadIdx.x;
    if (idx >= NGRAPH * D * D) return;
    float v = g_grams[idx];
    __nv_bfloat16 h = __float2bfloat16_rn(v);
    g_gh[idx] = h;
    g_gl[idx] = __float2bfloat16_rn(v - __bfloat162float(h));
}

// ---------------------------------------------------------------------------
// SIMT Gram kernel (same as R2): Gram[g] = X_g^T X_g, split-K 8-way
// ---------------------------------------------------------------------------
#define GSPLIT 8
#define GROWS  (LROWS / GSPLIT)

__global__ __launch_bounds__(256) void gram_kernel(const float* __restrict__ feats) {
    __shared__ float sX[32 * D];

    int graph = blockIdx.x >> 3;
    int chunk = blockIdx.x & 7;
    const float* Xg = feats + ((size_t)graph * LROWS + (size_t)chunk * GROWS) * D;

    int tid = threadIdx.x;
    int ta = tid >> 4;
    int tb = tid & 15;

    uint64_t acc[8][4];
#pragma unroll
    for (int r = 0; r < 8; r++)
#pragma unroll
        for (int p = 0; p < 4; p++) acc[r][p] = 0ull;

    for (int k0 = 0; k0 < GROWS; k0 += 32) {
        const float4* src = (const float4*)(Xg + (size_t)k0 * D);
        float4* dst = (float4*)sX;
#pragma unroll
        for (int q = 0; q < 4; q++) dst[tid + 256 * q] = src[tid + 256 * q];
        __syncthreads();

#pragma unroll 8
        for (int k = 0; k < 32; k++) {
            const float* row = sX + k * D;
            float4 A0 = *(const float4*)(row + 4 * ta);
            float4 A1 = *(const float4*)(row + 64 + 4 * ta);
            ulonglong2 B0 = *(const ulonglong2*)(row + 4 * tb);
            ulonglong2 B1 = *(const ulonglong2*)(row + 64 + 4 * tb);
            uint64_t da[8];
            da[0] = dup2(A0.x); da[1] = dup2(A0.y); da[2] = dup2(A0.z); da[3] = dup2(A0.w);
            da[4] = dup2(A1.x); da[5] = dup2(A1.y); da[6] = dup2(A1.z); da[7] = dup2(A1.w);
#pragma unroll
            for (int r = 0; r < 8; r++) {
                fma2(acc[r][0], da[r], B0.x);
                fma2(acc[r][1], da[r], B0.y);
                fma2(acc[r][2], da[r], B1.x);
                fma2(acc[r][3], da[r], B1.y);
            }
        }
        __syncthreads();
    }

    float* G = g_grams + (size_t)graph * D * D;
#pragma unroll
    for (int i = 0; i < 2; i++) {
#pragma unroll
        for (int c = 0; c < 4; c++) {
            int r = i * 4 + c;
            int grow = 64 * i + 4 * ta + c;
#pragma unroll
            for (int j = 0; j < 2; j++) {
                float f0, f1, f2, f3;
                unpack2(acc[r][2 * j], f0, f1);
                unpack2(acc[r][2 * j + 1], f2, f3);
                float* gp = G + grow * D + 64 * j + 4 * tb;
                atomicAdd(gp + 0, f0);
                atomicAdd(gp + 1, f1);
                atomicAdd(gp + 2, f2);
                atomicAdd(gp + 3, f3);
            }
        }
    }
}

// ---------------------------------------------------------------------------
// HMMA fused match kernel. 2048 blocks x 256 threads (8 warps), 64 rows/block.
// Warp (mt, nhalf): mt = w>>1 (16-row tile), nhalf = w&1 (64 output cols).
//
// smem (dynamic, b16 row stride SROW=136 -> LDSM slot stride 17 == 1 mod 8):
//   XH/XL: 64x136 bf16 (X hi/lo)        BH/BL: 128x136 (G hi/lo, then W hi/lo)
//   P1H/P1L, P2H/P2L: 64x136 product buffers
//
// Phase1 (3-pass): Y = X*G   (G symmetric -> row-major G is valid col-major B)
// Products: p_num = x*y -> P1, p_n2 = y*y -> P2 (x = xh+xl exact-ish)
// Phase2: num = P1*W (3-pass), n2 = P2*W (2-pass), then P1 <- x*x, n1 (2-pass)
// Epilogue: out = num / max(sqrt(n1*n2), eps)
// ---------------------------------------------------------------------------
#define SROW    136
#define OFF_XH  0u
#define OFF_XL  17408u
#define OFF_BH  34816u
#define OFF_BL  69632u
#define OFF_P1H 104448u
#define OFF_P1L 121856u
#define OFF_P2H 139264u
#define OFF_P2L 156672u
#define SMEM_NEED 174080

__global__ __launch_bounds__(256) void match_mma_kernel(
    const float* __restrict__ feats, float* __restrict__ out) {
    extern __shared__ __align__(16) char smem[];
    const uint32_t sb = smem_to_u32(smem);

    const int tid  = threadIdx.x;
    const int w    = tid >> 5;
    const int lane = tid & 31;
    const int mt   = w >> 1;       // m16 tile 0..3
    const int nh   = w & 1;        // n half (64 cols)
    const int r0   = blockIdx.x * 64;
    const int gi   = r0 >> 11;

    const uint32_t* ghp = (const uint32_t*)(g_gh + (size_t)(gi ^ 1) * D * D);
    const uint32_t* glp = (const uint32_t*)(g_gl + (size_t)(gi ^ 1) * D * D);
    const uint32_t* whp = (const uint32_t*)g_wh;
    const uint32_t* wlp = (const uint32_t*)g_wl;

    // ---- stage X (split hi/lo) ----
    {
        const float4* xs = (const float4*)(feats + (size_t)r0 * D);
#pragma unroll
        for (int q = 0; q < 8; q++) {
            int idx = tid + 256 * q;
            int row = idx >> 5, c4 = idx & 31;
            float4 f = xs[idx];
            uint32_t h01 = pack_bf2(f.x, f.y);
            uint32_t h23 = pack_bf2(f.z, f.w);
            uint32_t l01 = pack_bf2(f.x - bfu_lo(h01), f.y - bfu_hi(h01));
            uint32_t l23 = pack_bf2(f.z - bfu_lo(h23), f.w - bfu_hi(h23));
            uint32_t off = (uint32_t)(row * SROW + 4 * c4) * 2;
            *(uint2*)(smem + OFF_XH + off) = make_uint2(h01, h23);
            *(uint2*)(smem + OFF_XL + off) = make_uint2(l01, l23);
        }
    }
    // ---- stage G hi/lo ----
#pragma unroll
    for (int q = 0; q < 32; q++) {
        int idx = tid + 256 * q;
        int row = idx >> 6, cp = idx & 63;
        uint32_t off = (uint32_t)(row * SROW + 2 * cp) * 2;
        *(uint32_t*)(smem + OFF_BH + off) = ghp[idx];
        *(uint32_t*)(smem + OFF_BL + off) = glp[idx];
    }
    __syncthreads();

    // fragment base offsets for this lane
    const uint32_t arow = mt * 16 + (lane & 7) + ((lane >> 3) & 1) * 8;
    const uint32_t acolh = (lane >> 4) * 8;       // +8 cols for lanes 16-31
    const int bl_  = lane & 15;
    const uint32_t brow_l = (uint32_t)(bl_ & 7);
    const uint32_t bcol_l = (uint32_t)(((bl_ >> 3) & 1) * 8);

    // ---------------- Phase 1: Y = X * G (3-pass) ----------------
    float accY[8][4];
#pragma unroll
    for (int t = 0; t < 8; t++)
#pragma unroll
        for (int v = 0; v < 4; v++) accY[t][v] = 0.f;

#pragma unroll
    for (int j = 0; j < 8; j++) {
        uint32_t aoff = (arow * SROW + j * 16 + acolh) * 2;
        uint32_t ah[4], al[4];
        ldsm4(ah, sb + OFF_XH + aoff);
        ldsm4(al, sb + OFF_XL + aoff);
#pragma unroll
        for (int t = 0; t < 8; t++) {
            uint32_t brow = (uint32_t)(nh * 64 + t * 8) + brow_l;
            uint32_t boff = (brow * SROW + j * 16 + bcol_l) * 2;
            uint32_t bh[2], bl2[2];
            ldsm2(bh,  sb + OFF_BH + boff);
            ldsm2(bl2, sb + OFF_BL + boff);
            mma16816(accY[t], ah, bh);
            mma16816(accY[t], al, bh);
            mma16816(accY[t], ah, bl2);
        }
    }
    __syncthreads();   // done reading G; BH/BL can be overwritten

    // ---- stage W hi/lo (over G) ----
#pragma unroll
    for (int q = 0; q < 32; q++) {
        int idx = tid + 256 * q;
        int row = idx >> 6, cp = idx & 63;
        uint32_t off = (uint32_t)(row * SROW + 2 * cp) * 2;
        *(uint32_t*)(smem + OFF_BH + off) = whp[idx];
        *(uint32_t*)(smem + OFF_BL + off) = wlp[idx];
    }

    // ---- products: p_num = x*y -> P1, p_n2 = y*y -> P2 ----
    const int ra = lane >> 2;
    const int ca = (lane & 3) * 2;
#pragma unroll
    for (int t = 0; t < 8; t++) {
        int col = nh * 64 + t * 8 + ca;
#pragma unroll
        for (int h2 = 0; h2 < 2; h2++) {
            int row = mt * 16 + ra + 8 * h2;
            uint32_t off = (uint32_t)(row * SROW + col) * 2;
            uint32_t xh2 = *(const uint32_t*)(smem + OFF_XH + off);
            uint32_t xl2 = *(const uint32_t*)(smem + OFF_XL + off);
            float x0 = bfu_lo(xh2) + bfu_lo(xl2);
            float x1 = bfu_hi(xh2) + bfu_hi(xl2);
            float y0 = accY[t][2 * h2], y1 = accY[t][2 * h2 + 1];

            float p0 = x0 * y0, p1 = x1 * y1;
            uint32_t ph = pack_bf2(p0, p1);
            uint32_t pl = pack_bf2(p0 - bfu_lo(ph), p1 - bfu_hi(ph));
            *(uint32_t*)(smem + OFF_P1H + off) = ph;
            *(uint32_t*)(smem + OFF_P1L + off) = pl;

            float q0 = y0 * y0, q1 = y1 * y1;
            uint32_t qh = pack_bf2(q0, q1);
            uint32_t ql = pack_bf2(q0 - bfu_lo(qh), q1 - bfu_hi(qh));
            *(uint32_t*)(smem + OFF_P2H + off) = qh;
            *(uint32_t*)(smem + OFF_P2L + off) = ql;
        }
    }
    __syncthreads();

    // ---------------- Phase 2a: num = P1*W (3-pass), n2 = P2*W (2-pass) ------
    float accN[8][4], accC[8][4];
#pragma unroll
    for (int t = 0; t < 8; t++)
#pragma unroll
        for (int v = 0; v < 4; v++) { accN[t][v] = 0.f; accC[t][v] = 0.f; }

#pragma unroll
    for (int j = 0; j < 8; j++) {
        uint32_t aoff = (arow * SROW + j * 16 + acolh) * 2;
        uint32_t n_h[4], n_l[4], c_h[4], c_l[4];
        ldsm4(n_h, sb + OFF_P1H + aoff);
        ldsm4(n_l, sb + OFF_P1L + aoff);
        ldsm4(c_h, sb + OFF_P2H + aoff);
        ldsm4(c_l, sb + OFF_P2L + aoff);
#pragma unroll
        for (int t = 0; t < 8; t++) {
            uint32_t brow = (uint32_t)(nh * 64 + t * 8) + brow_l;
            uint32_t boff = (brow * SROW + j * 16 + bcol_l) * 2;
            uint32_t bh[2], bl2[2];
            ldsm2(bh,  sb + OFF_BH + boff);
            ldsm2(bl2, sb + OFF_BL + boff);
            mma16816(accN[t], n_h, bh);
            mma16816(accN[t], n_l, bh);
            mma16816(accN[t], n_h, bl2);
            mma16816(accC[t], c_h, bh);
            mma16816(accC[t], c_l, bh);
        }
    }
    __syncthreads();   // done reading P1

    // ---- P1 <- p_n1 = x*x ----
#pragma unroll
    for (int t = 0; t < 8; t++) {
        int col = nh * 64 + t * 8 + ca;
#pragma unroll
        for (int h2 = 0; h2 < 2; h2++) {
            int row = mt * 16 + ra + 8 * h2;
            uint32_t off = (uint32_t)(row * SROW + col) * 2;
            uint32_t xh2 = *(const uint32_t*)(smem + OFF_XH + off);
            uint32_t xl2 = *(const uint32_t*)(smem + OFF_XL + off);
            float x0 = bfu_lo(xh2) + bfu_lo(xl2);
            float x1 = bfu_hi(xh2) + bfu_hi(xl2);
            float p0 = x0 * x0, p1 = x1 * x1;
            uint32_t ph = pack_bf2(p0, p1);
            uint32_t pl = pack_bf2(p0 - bfu_lo(ph), p1 - bfu_hi(ph));
            *(uint32_t*)(smem + OFF_P1H + off) = ph;
            *(uint32_t*)(smem + OFF_P1L + off) = pl;
        }
    }
    __syncthreads();

    // ---------------- Phase 2b: n1 = P1*W (2-pass) ----------------
    float accB[8][4];
#pragma unroll
    for (int t = 0; t < 8; t++)
#pragma unroll
        for (int v = 0; v < 4; v++) accB[t][v] = 0.f;

#pragma unroll
    for (int j = 0; j < 8; j++) {
        uint32_t aoff = (arow * SROW + j * 16 + acolh) * 2;
        uint32_t b_h[4], b_l[4];
        ldsm4(b_h, sb + OFF_P1H + aoff);
        ldsm4(b_l, sb + OFF_P1L + aoff);
#pragma unroll
        for (int t = 0; t < 8; t++) {
            uint32_t brow = (uint32_t)(nh * 64 + t * 8) + brow_l;
            uint32_t boff = (brow * SROW + j * 16 + bcol_l) * 2;
            uint32_t bh[2];
            ldsm2(bh, sb + OFF_BH + boff);
            mma16816(accB[t], b_h, bh);
            mma16816(accB[t], b_l, bh);
        }
    }

    // ---------------- Epilogue ----------------
#pragma unroll
    for (int t = 0; t < 8; t++) {
        int col = nh * 64 + t * 8 + ca;
#pragma unroll
        for (int h2 = 0; h2 < 2; h2++) {
            int row = r0 + mt * 16 + ra + 8 * h2;
            float n0v = accN[t][2 * h2], n1v = accN[t][2 * h2 + 1];
            float b0v = accB[t][2 * h2], b1v = accB[t][2 * h2 + 1];
            float c0v = accC[t][2 * h2], c1v = accC[t][2 * h2 + 1];
            float2 o;
            o.x = n0v / fmaxf(sqrtf(b0v * c0v), EPS);
            o.y = n1v / fmaxf(sqrtf(b1v * c1v), EPS);
            *(float2*)(out + (size_t)row * D + col) = o;
        }
    }
}

// ---------------------------------------------------------------------------
extern "C" void kernel_launch(void* const* d_in, const int* in_sizes, int n_in,
                              void* d_out, int out_size) {
    const float* feats = (const float*)d_in[0];
    const float* mp_w  = (const float*)d_in[1];
    float* out = (float*)d_out;

    static bool attr_done = false;
    if (!attr_done) {
        cudaFuncSetAttribute(match_mma_kernel,
                             cudaFuncAttributeMaxDynamicSharedMemorySize, SMEM_NEED);
        attr_done = true;
    }

    int N = in_sizes[0] / D;   // 131072 rows

    zero_grams_kernel<<<(NGRAPH * D * D / 4 + 255) / 256, 256>>>();
    wcvt_kernel<<<(D * D + 255) / 256, 256>>>(mp_w);
    gram_kernel<<<NGRAPH * GSPLIT, 256>>>(feats);
    gram_cvt_kernel<<<(NGRAPH * D * D + 255) / 256, 256>>>();
    match_mma_kernel<<<N / 64, 256, SMEM_NEED>>>(feats, out);
}

// round 5
// speedup vs baseline: 3.2321x; 1.2583x over previous
#include <cuda_runtime.h>
#include <cuda_bf16.h>
#include <math.h>
#include <stdint.h>

#define D      128
#define NGRAPH 64
#define LROWS  2048
#define EPS    1e-8f

// ---------------------------------------------------------------------------
// Global scratch
// ---------------------------------------------------------------------------
__device__ float         g_grams[NGRAPH * D * D];
__device__ __nv_bfloat16 g_gh[NGRAPH * D * D];
__device__ __nv_bfloat16 g_gl[NGRAPH * D * D];
__device__ __nv_bfloat16 g_wh[D * D];
__device__ __nv_bfloat16 g_wl[D * D];

// ---------------------------------------------------------------------------
// Helpers
// ---------------------------------------------------------------------------
__device__ __forceinline__ uint32_t smem_to_u32(const void* p) {
    uint32_t a;
    asm("{ .reg .u64 t; cvta.to.shared.u64 t, %1; cvt.u32.u64 %0, t; }" : "=r"(a) : "l"(p));
    return a;
}

// pack two fp32 -> bf16x2 (first arg in low half)
__device__ __forceinline__ uint32_t pack_bf2(float lo, float hi) {
    uint32_t r;
    asm("cvt.rn.bf16x2.f32 %0, %1, %2;" : "=r"(r) : "f"(hi), "f"(lo));
    return r;
}
__device__ __forceinline__ float bfu_lo(uint32_t u) { return __uint_as_float(u << 16); }
__device__ __forceinline__ float bfu_hi(uint32_t u) { return __uint_as_float(u & 0xFFFF0000u); }

__device__ __forceinline__ void ldsm4(uint32_t* r, uint32_t addr) {
    asm volatile("ldmatrix.sync.aligned.m8n8.x4.shared.b16 {%0,%1,%2,%3}, [%4];"
        : "=r"(r[0]), "=r"(r[1]), "=r"(r[2]), "=r"(r[3]) : "r"(addr));
}
__device__ __forceinline__ void ldsm4t(uint32_t* r, uint32_t addr) {
    asm volatile("ldmatrix.sync.aligned.m8n8.x4.trans.shared.b16 {%0,%1,%2,%3}, [%4];"
        : "=r"(r[0]), "=r"(r[1]), "=r"(r[2]), "=r"(r[3]) : "r"(addr));
}
__device__ __forceinline__ void mma16816(float* c, const uint32_t* a, const uint32_t* b) {
    asm volatile("mma.sync.aligned.m16n8k16.row.col.f32.bf16.bf16.f32 "
        "{%0,%1,%2,%3}, {%4,%5,%6,%7}, {%8,%9}, {%0,%1,%2,%3};"
        : "+f"(c[0]), "+f"(c[1]), "+f"(c[2]), "+f"(c[3])
        : "r"(a[0]), "r"(a[1]), "r"(a[2]), "r"(a[3]), "r"(b[0]), "r"(b[1]));
}

// ---------------------------------------------------------------------------
__global__ void zero_grams_kernel() {
    int idx = blockIdx.x * blockDim.x + threadIdx.x;
    float4* p = (float4*)g_grams;
    if (idx < (NGRAPH * D * D) / 4) p[idx] = make_float4(0.f, 0.f, 0.f, 0.f);
}

__global__ void wcvt_kernel(const float* __restrict__ mp_w) {
    int idx = blockIdx.x * blockDim.x + threadIdx.x;
    if (idx >= D * D) return;
    float v = mp_w[idx];
    float w2 = v * v;
    __nv_bfloat16 h = __float2bfloat16_rn(w2);
    g_wh[idx] = h;
    g_wl[idx] = __float2bfloat16_rn(w2 - __bfloat162float(h));
}

__global__ void gram_cvt_kernel() {
    int idx = blockIdx.x * blockDim.x + threadIdx.x;
    if (idx >= NGRAPH * D * D) return;
    float v = g_grams[idx];
    __nv_bfloat16 h = __float2bfloat16_rn(v);
    g_gh[idx] = h;
    g_gl[idx] = __float2bfloat16_rn(v - __bfloat162float(h));
}

// ---------------------------------------------------------------------------
// HMMA Gram kernel: G[g] = X_g^T X_g.  Grid = 64 graphs x 4 split-K blocks.
// Block: 256 thr, 8 warps; warp w owns m16 tile (rows d = 16w..16w+15), n=128.
// K = 512 rows per block, staged in 8 chunks of 64 rows (hi/lo bf16 split).
// A and B fragments both come from the [l][d] X tile via ldmatrix.trans.
// 3-pass: AhBh + AlBh + AhBl. fp32 atomicAdd reduction into g_grams.
// ---------------------------------------------------------------------------
#define GSROW 136   // b16 row stride: 272B -> trans-LDSM lane stride 68 words (mod 32 = 4)

__global__ __launch_bounds__(256) void gram_mma_kernel(const float* __restrict__ feats) {
    __shared__ __nv_bfloat16 sXH[64 * GSROW];
    __shared__ __nv_bfloat16 sXL[64 * GSROW];
    const uint32_t sbh = smem_to_u32(sXH);
    const uint32_t sbl = smem_to_u32(sXL);

    const int tid  = threadIdx.x;
    const int w    = tid >> 5;
    const int lane = tid & 31;
    const int graph = blockIdx.x >> 2;
    const int split = blockIdx.x & 3;
    const int m0   = w * 16;

    const float* Xg = feats + ((size_t)graph * LROWS + (size_t)split * 512) * D;

    const int g   = lane >> 3;
    const int li  = lane & 7;
    // A (trans): slot order (m0,k0),(m8,k0),(m0,k8),(m8,k8); stored [l][d]
    const uint32_t arl  = (uint32_t)((g >> 1) * 8 + li);     // l-row within k16 (+j*16)
    const uint32_t acol = (uint32_t)(m0 + (g & 1) * 8);      // d-col
    // B (trans): slot order (n_t,k0),(n_t,k8),(n_t1,k0),(n_t1,k8)
    const uint32_t brl  = (uint32_t)((g & 1) * 8 + li);      // l-row within k16
    const uint32_t bct  = (uint32_t)(g >> 1);                // +0/+1 n8 tile

    float acc[16][4];
#pragma unroll
    for (int t = 0; t < 16; t++)
#pragma unroll
        for (int v = 0; v < 4; v++) acc[t][v] = 0.f;

    for (int chunk = 0; chunk < 8; chunk++) {
        // stage 64 rows x 128 cols, hi/lo split
        const float4* xs = (const float4*)(Xg + (size_t)chunk * 64 * D);
#pragma unroll
        for (int q = 0; q < 8; q++) {
            int idx = tid + 256 * q;
            int row = idx >> 5, c4 = idx & 31;
            float4 f = xs[idx];
            uint32_t h01 = pack_bf2(f.x, f.y);
            uint32_t h23 = pack_bf2(f.z, f.w);
            uint32_t l01 = pack_bf2(f.x - bfu_lo(h01), f.y - bfu_hi(h01));
            uint32_t l23 = pack_bf2(f.z - bfu_lo(h23), f.w - bfu_hi(h23));
            *(uint2*)((char*)sXH + (uint32_t)(row * GSROW + 4 * c4) * 2) = make_uint2(h01, h23);
            *(uint2*)((char*)sXL + (uint32_t)(row * GSROW + 4 * c4) * 2) = make_uint2(l01, l23);
        }
        __syncthreads();

#pragma unroll
        for (int j = 0; j < 4; j++) {
            uint32_t aoff = ((j * 16 + arl) * GSROW + acol) * 2;
            uint32_t ah[4], al[4];
            ldsm4t(ah, sbh + aoff);
            ldsm4t(al, sbl + aoff);
#pragma unroll
            for (int tp = 0; tp < 8; tp++) {
                uint32_t boff = ((j * 16 + brl) * GSROW + (2 * tp + bct) * 8) * 2;
                uint32_t bh[4], bl[4];
                ldsm4t(bh, sbh + boff);
                ldsm4t(bl, sbl + boff);
                mma16816(acc[2 * tp],     ah, bh);
                mma16816(acc[2 * tp],     al, bh);
                mma16816(acc[2 * tp],     ah, bl);
                mma16816(acc[2 * tp + 1], ah, bh + 2);
                mma16816(acc[2 * tp + 1], al, bh + 2);
                mma16816(acc[2 * tp + 1], ah, bl + 2);
            }
        }
        __syncthreads();
    }

    // reduce: C frag rows m0+ra (+8), cols t*8 + ca (+1)
    float* G = g_grams + (size_t)graph * D * D;
    const int ra = lane >> 2;
    const int ca = (lane & 3) * 2;
#pragma unroll
    for (int t = 0; t < 16; t++) {
        int col = t * 8 + ca;
        atomicAdd(&G[(m0 + ra) * D + col],     acc[t][0]);
        atomicAdd(&G[(m0 + ra) * D + col + 1], acc[t][1]);
        atomicAdd(&G[(m0 + ra + 8) * D + col],     acc[t][2]);
        atomicAdd(&G[(m0 + ra + 8) * D + col + 1], acc[t][3]);
    }
}

// ---------------------------------------------------------------------------
// HMMA fused match kernel. 2048 blocks x 256 threads (8 warps), 64 rows/block.
// Warp (mt, nhalf): mt = w>>1 (m16 tile), nhalf = w&1 (64 output cols).
// B fragments: ldsm4 covering two n8 tiles per load (halved LDSM count vs R4).
// ---------------------------------------------------------------------------
#define SROW    136
#define OFF_XH  0u
#define OFF_XL  17408u
#define OFF_BH  34816u
#define OFF_BL  69632u
#define OFF_P1H 104448u
#define OFF_P1L 121856u
#define OFF_P2H 139264u
#define OFF_P2L 156672u
#define SMEM_NEED 174080

__global__ __launch_bounds__(256) void match_mma_kernel(
    const float* __restrict__ feats, float* __restrict__ out) {
    extern __shared__ __align__(16) char smem[];
    const uint32_t sb = smem_to_u32(smem);

    const int tid  = threadIdx.x;
    const int w    = tid >> 5;
    const int lane = tid & 31;
    const int mt   = w >> 1;       // m16 tile 0..3
    const int nh   = w & 1;        // n half (64 cols)
    const int r0   = blockIdx.x * 64;
    const int gi   = r0 >> 11;

    const uint32_t* ghp = (const uint32_t*)(g_gh + (size_t)(gi ^ 1) * D * D);
    const uint32_t* glp = (const uint32_t*)(g_gl + (size_t)(gi ^ 1) * D * D);
    const uint32_t* whp = (const uint32_t*)g_wh;
    const uint32_t* wlp = (const uint32_t*)g_wl;

    // ---- stage X (split hi/lo) ----
    {
        const float4* xs = (const float4*)(feats + (size_t)r0 * D);
#pragma unroll
        for (int q = 0; q < 8; q++) {
            int idx = tid + 256 * q;
            int row = idx >> 5, c4 = idx & 31;
            float4 f = xs[idx];
            uint32_t h01 = pack_bf2(f.x, f.y);
            uint32_t h23 = pack_bf2(f.z, f.w);
            uint32_t l01 = pack_bf2(f.x - bfu_lo(h01), f.y - bfu_hi(h01));
            uint32_t l23 = pack_bf2(f.z - bfu_lo(h23), f.w - bfu_hi(h23));
            uint32_t off = (uint32_t)(row * SROW + 4 * c4) * 2;
            *(uint2*)(smem + OFF_XH + off) = make_uint2(h01, h23);
            *(uint2*)(smem + OFF_XL + off) = make_uint2(l01, l23);
        }
    }
    // ---- stage G hi/lo ----
#pragma unroll
    for (int q = 0; q < 32; q++) {
        int idx = tid + 256 * q;
        int row = idx >> 6, cp = idx & 63;
        uint32_t off = (uint32_t)(row * SROW + 2 * cp) * 2;
        *(uint32_t*)(smem + OFF_BH + off) = ghp[idx];
        *(uint32_t*)(smem + OFF_BL + off) = glp[idx];
    }
    __syncthreads();

    // fragment lane offsets
    const uint32_t arow = mt * 16 + (lane & 7) + ((lane >> 3) & 1) * 8;
    const uint32_t acolh = (lane >> 4) * 8;
    // B via ldsm4 (non-trans), two n8 tiles per load:
    // group g: slot (t + (g>>1), k + (g&1)*8)
    const int g    = lane >> 3;
    const uint32_t bnrow = (uint32_t)((g >> 1) * 8 + (lane & 7));  // + tp*16 + nh*64
    const uint32_t bkoff = (uint32_t)((g & 1) * 8);                // + j*16

    // ---------------- Phase 1: Y = X * G (3-pass) ----------------
    float accY[8][4];
#pragma unroll
    for (int t = 0; t < 8; t++)
#pragma unroll
        for (int v = 0; v < 4; v++) accY[t][v] = 0.f;

#pragma unroll
    for (int j = 0; j < 8; j++) {
        uint32_t aoff = (arow * SROW + j * 16 + acolh) * 2;
        uint32_t ah[4], al[4];
        ldsm4(ah, sb + OFF_XH + aoff);
        ldsm4(al, sb + OFF_XL + aoff);
#pragma unroll
        for (int tp = 0; tp < 4; tp++) {
            uint32_t boff = (((uint32_t)(nh * 64 + tp * 16) + bnrow) * SROW + j * 16 + bkoff) * 2;
            uint32_t bh[4], bl2[4];
            ldsm4(bh,  sb + OFF_BH + boff);
            ldsm4(bl2, sb + OFF_BL + boff);
            mma16816(accY[2 * tp], ah, bh);
            mma16816(accY[2 * tp], al, bh);
            mma16816(accY[2 * tp], ah, bl2);
            mma16816(accY[2 * tp + 1], ah, bh + 2);
            mma16816(accY[2 * tp + 1], al, bh + 2);
            mma16816(accY[2 * tp + 1], ah, bl2 + 2);
        }
    }
    __syncthreads();   // done reading G; BH/BL can be overwritten

    // ---- stage W hi/lo (over G) ----
#pragma unroll
    for (int q = 0; q < 32; q++) {
        int idx = tid + 256 * q;
        int row = idx >> 6, cp = idx & 63;
        uint32_t off = (uint32_t)(row * SROW + 2 * cp) * 2;
        *(uint32_t*)(smem + OFF_BH + off) = whp[idx];
        *(uint32_t*)(smem + OFF_BL + off) = wlp[idx];
    }

    // ---- products: p_num = x*y -> P1, p_n2 = y*y -> P2 ----
    const int ra = lane >> 2;
    const int ca = (lane & 3) * 2;
#pragma unroll
    for (int t = 0; t < 8; t++) {
        int col = nh * 64 + t * 8 + ca;
#pragma unroll
        for (int h2 = 0; h2 < 2; h2++) {
            int row = mt * 16 + ra + 8 * h2;
            uint32_t off = (uint32_t)(row * SROW + col) * 2;
            uint32_t xh2 = *(const uint32_t*)(smem + OFF_XH + off);
            uint32_t xl2 = *(const uint32_t*)(smem + OFF_XL + off);
            float x0 = bfu_lo(xh2) + bfu_lo(xl2);
            float x1 = bfu_hi(xh2) + bfu_hi(xl2);
            float y0 = accY[t][2 * h2], y1 = accY[t][2 * h2 + 1];

            float p0 = x0 * y0, p1 = x1 * y1;
            uint32_t ph = pack_bf2(p0, p1);
            uint32_t pl = pack_bf2(p0 - bfu_lo(ph), p1 - bfu_hi(ph));
            *(uint32_t*)(smem + OFF_P1H + off) = ph;
            *(uint32_t*)(smem + OFF_P1L + off) = pl;

            float q0 = y0 * y0, q1 = y1 * y1;
            uint32_t qh = pack_bf2(q0, q1);
            uint32_t ql = pack_bf2(q0 - bfu_lo(qh), q1 - bfu_hi(qh));
            *(uint32_t*)(smem + OFF_P2H + off) = qh;
            *(uint32_t*)(smem + OFF_P2L + off) = ql;
        }
    }
    __syncthreads();

    // ---------------- Phase 2a: num = P1*W (3-pass), n2 = P2*W (2-pass) ------
    float accN[8][4], accC[8][4];
#pragma unroll
    for (int t = 0; t < 8; t++)
#pragma unroll
        for (int v = 0; v < 4; v++) { accN[t][v] = 0.f; accC[t][v] = 0.f; }

#pragma unroll
    for (int j = 0; j < 8; j++) {
        uint32_t aoff = (arow * SROW + j * 16 + acolh) * 2;
        uint32_t n_h[4], n_l[4], c_h[4], c_l[4];
        ldsm4(n_h, sb + OFF_P1H + aoff);
        ldsm4(n_l, sb + OFF_P1L + aoff);
        ldsm4(c_h, sb + OFF_P2H + aoff);
        ldsm4(c_l, sb + OFF_P2L + aoff);
#pragma unroll
        for (int tp = 0; tp < 4; tp++) {
            uint32_t boff = (((uint32_t)(nh * 64 + tp * 16) + bnrow) * SROW + j * 16 + bkoff) * 2;
            uint32_t bh[4], bl2[4];
            ldsm4(bh,  sb + OFF_BH + boff);
            ldsm4(bl2, sb + OFF_BL + boff);
            mma16816(accN[2 * tp], n_h, bh);
            mma16816(accN[2 * tp], n_l, bh);
            mma16816(accN[2 * tp], n_h, bl2);
            mma16816(accC[2 * tp], c_h, bh);
            mma16816(accC[2 * tp], c_l, bh);
            mma16816(accN[2 * tp + 1], n_h, bh + 2);
            mma16816(accN[2 * tp + 1], n_l, bh + 2);
            mma16816(accN[2 * tp + 1], n_h, bl2 + 2);
            mma16816(accC[2 * tp + 1], c_h, bh + 2);
            mma16816(accC[2 * tp + 1], c_l, bh + 2);
        }
    }
    __syncthreads();   // done reading P1

    // ---- P1 <- p_n1 = x*x ----
#pragma unroll
    for (int t = 0; t < 8; t++) {
        int col = nh * 64 + t * 8 + ca;
#pragma unroll
        for (int h2 = 0; h2 < 2; h2++) {
            int row = mt * 16 + ra + 8 * h2;
            uint32_t off = (uint32_t)(row * SROW + col) * 2;
            uint32_t xh2 = *(const uint32_t*)(smem + OFF_XH + off);
            uint32_t xl2 = *(const uint32_t*)(smem + OFF_XL + off);
            float x0 = bfu_lo(xh2) + bfu_lo(xl2);
            float x1 = bfu_hi(xh2) + bfu_hi(xl2);
            float p0 = x0 * x0, p1 = x1 * x1;
            uint32_t ph = pack_bf2(p0, p1);
            uint32_t pl = pack_bf2(p0 - bfu_lo(ph), p1 - bfu_hi(ph));
            *(uint32_t*)(smem + OFF_P1H + off) = ph;
            *(uint32_t*)(smem + OFF_P1L + off) = pl;
        }
    }
    __syncthreads();

    // ---------------- Phase 2b: n1 = P1*W (2-pass) ----------------
    float accB[8][4];
#pragma unroll
    for (int t = 0; t < 8; t++)
#pragma unroll
        for (int v = 0; v < 4; v++) accB[t][v] = 0.f;

#pragma unroll
    for (int j = 0; j < 8; j++) {
        uint32_t aoff = (arow * SROW + j * 16 + acolh) * 2;
        uint32_t b_h[4], b_l[4];
        ldsm4(b_h, sb + OFF_P1H + aoff);
        ldsm4(b_l, sb + OFF_P1L + aoff);
#pragma unroll
        for (int tp = 0; tp < 4; tp++) {
            uint32_t boff = (((uint32_t)(nh * 64 + tp * 16) + bnrow) * SROW + j * 16 + bkoff) * 2;
            uint32_t bh[4];
            ldsm4(bh, sb + OFF_BH + boff);
            mma16816(accB[2 * tp], b_h, bh);
            mma16816(accB[2 * tp], b_l, bh);
            mma16816(accB[2 * tp + 1], b_h, bh + 2);
            mma16816(accB[2 * tp + 1], b_l, bh + 2);
        }
    }

    // ---------------- Epilogue ----------------
#pragma unroll
    for (int t = 0; t < 8; t++) {
        int col = nh * 64 + t * 8 + ca;
#pragma unroll
        for (int h2 = 0; h2 < 2; h2++) {
            int row = r0 + mt * 16 + ra + 8 * h2;
            float n0v = accN[t][2 * h2], n1v = accN[t][2 * h2 + 1];
            float b0v = accB[t][2 * h2], b1v = accB[t][2 * h2 + 1];
            float c0v = accC[t][2 * h2], c1v = accC[t][2 * h2 + 1];
            float2 o;
            o.x = n0v / fmaxf(sqrtf(b0v * c0v), EPS);
            o.y = n1v / fmaxf(sqrtf(b1v * c1v), EPS);
            *(float2*)(out + (size_t)row * D + col) = o;
        }
    }
}

// ---------------------------------------------------------------------------
extern "C" void kernel_launch(void* const* d_in, const int* in_sizes, int n_in,
                              void* d_out, int out_size) {
    const float* feats = (const float*)d_in[0];
    const float* mp_w  = (const float*)d_in[1];
    float* out = (float*)d_out;

    static bool attr_done = false;
    if (!attr_done) {
        cudaFuncSetAttribute(match_mma_kernel,
                             cudaFuncAttributeMaxDynamicSharedMemorySize, SMEM_NEED);
        attr_done = true;
    }

    int N = in_sizes[0] / D;   // 131072 rows

    zero_grams_kernel<<<(NGRAPH * D * D / 4 + 255) / 256, 256>>>();
    wcvt_kernel<<<(D * D + 255) / 256, 256>>>(mp_w);
    gram_mma_kernel<<<NGRAPH * 4, 256>>>(feats);
    gram_cvt_kernel<<<(NGRAPH * D * D + 255) / 256, 256>>>();
    match_mma_kernel<<<N / 64, 256, SMEM_NEED>>>(feats, out);
}

// round 6
// speedup vs baseline: 3.8537x; 1.1923x over previous
#include <cuda_runtime.h>
#include <cuda_fp16.h>
#include <math.h>
#include <stdint.h>

#define D      128
#define NGRAPH 64
#define LROWS  2048
#define EPS    1e-8f
#define YSCALE 0.015625f   // 2^-6, exact

// ---------------------------------------------------------------------------
// Global scratch
// ---------------------------------------------------------------------------
__device__ float  g_grams[2 * NGRAPH * D * D];   // two split-K partials
__device__ __half g_gh[NGRAPH * D * D];
__device__ __half g_gl[NGRAPH * D * D];
__device__ __half g_wh[D * D];
__device__ __half g_wl[D * D];

// ---------------------------------------------------------------------------
// Helpers
// ---------------------------------------------------------------------------
__device__ __forceinline__ uint32_t smem_to_u32(const void* p) {
    uint32_t a;
    asm("{ .reg .u64 t; cvta.to.shared.u64 t, %1; cvt.u32.u64 %0, t; }" : "=r"(a) : "l"(p));
    return a;
}
__device__ __forceinline__ uint32_t h2u(__half2 h) { return *(uint32_t*)&h; }

__device__ __forceinline__ void ldsm4(uint32_t* r, uint32_t addr) {
    asm volatile("ldmatrix.sync.aligned.m8n8.x4.shared.b16 {%0,%1,%2,%3}, [%4];"
        : "=r"(r[0]), "=r"(r[1]), "=r"(r[2]), "=r"(r[3]) : "r"(addr));
}
__device__ __forceinline__ void ldsm4t(uint32_t* r, uint32_t addr) {
    asm volatile("ldmatrix.sync.aligned.m8n8.x4.trans.shared.b16 {%0,%1,%2,%3}, [%4];"
        : "=r"(r[0]), "=r"(r[1]), "=r"(r[2]), "=r"(r[3]) : "r"(addr));
}
__device__ __forceinline__ void mma16816(float* c, const uint32_t* a, const uint32_t* b) {
    asm volatile("mma.sync.aligned.m16n8k16.row.col.f32.f16.f16.f32 "
        "{%0,%1,%2,%3}, {%4,%5,%6,%7}, {%8,%9}, {%0,%1,%2,%3};"
        : "+f"(c[0]), "+f"(c[1]), "+f"(c[2]), "+f"(c[3])
        : "r"(a[0]), "r"(a[1]), "r"(a[2]), "r"(a[3]), "r"(b[0]), "r"(b[1]));
}

// split f.x,f.y -> (hi half2, lo half2)
__device__ __forceinline__ void split2(float a, float b, uint32_t& hi, uint32_t& lo) {
    __half2 h = __floats2half2_rn(a, b);
    float2 hf = __half22float2(h);
    __half2 l = __floats2half2_rn(a - hf.x, b - hf.y);
    hi = h2u(h); lo = h2u(l);
}

// ---------------------------------------------------------------------------
// wcvt: w2 = mp_w^2 split to fp16 hi/lo, row-major [p][d] (K-major for B)
// ---------------------------------------------------------------------------
__global__ void wcvt_kernel(const float* __restrict__ mp_w) {
    int idx = blockIdx.x * blockDim.x + threadIdx.x;
    if (idx >= D * D) return;
    float v = mp_w[idx];
    float w2 = v * v;
    __half h = __float2half_rn(w2);
    g_wh[idx] = h;
    g_wl[idx] = __float2half_rn(w2 - __half2float(h));
}

// gram partial-sum + fp16 split, vectorized x4
__global__ void gram_cvt_kernel() {
    int idx = blockIdx.x * blockDim.x + threadIdx.x;   // 0 .. NGRAPH*D*D/4
    if (idx >= NGRAPH * D * D / 4) return;
    float4 a = *(const float4*)(g_grams + 4 * (size_t)idx);
    float4 b = *(const float4*)(g_grams + NGRAPH * D * D + 4 * (size_t)idx);
    float4 v = make_float4(a.x + b.x, a.y + b.y, a.z + b.z, a.w + b.w);
    uint32_t h01, l01, h23, l23;
    split2(v.x, v.y, h01, l01);
    split2(v.z, v.w, h23, l23);
    *(uint2*)(g_gh + 4 * (size_t)idx) = make_uint2(h01, h23);
    *(uint2*)(g_gl + 4 * (size_t)idx) = make_uint2(l01, l23);
}

// ---------------------------------------------------------------------------
// HMMA Gram kernel (fp16, 2-pass): G[g] = X_g^T X_g.
// Grid = 64 graphs x 2 split-K blocks = 128 (single wave). K=1024 rows/block,
// staged in 16 chunks of 64. Warp w owns m16 tile (d-rows 16w..16w+15), n=128.
// Passes: AhBh + AlBh. Disjoint partial-sum output (no atomics).
// ---------------------------------------------------------------------------
#define GSROW 136

__global__ __launch_bounds__(256) void gram_mma_kernel(const float* __restrict__ feats) {
    __shared__ __half sXH[64 * GSROW];
    __shared__ __half sXL[64 * GSROW];
    const uint32_t sbh = smem_to_u32(sXH);
    const uint32_t sbl = smem_to_u32(sXL);

    const int tid  = threadIdx.x;
    const int w    = tid >> 5;
    const int lane = tid & 31;
    const int graph = blockIdx.x >> 1;
    const int split = blockIdx.x & 1;
    const int m0   = w * 16;

    const float* Xg = feats + ((size_t)graph * LROWS + (size_t)split * 1024) * D;

    const int g   = lane >> 3;
    const int li  = lane & 7;
    const uint32_t arl  = (uint32_t)((g >> 1) * 8 + li);
    const uint32_t acol = (uint32_t)(m0 + (g & 1) * 8);
    const uint32_t brl  = (uint32_t)((g & 1) * 8 + li);
    const uint32_t bct  = (uint32_t)(g >> 1);

    float acc[16][4];
#pragma unroll
    for (int t = 0; t < 16; t++)
#pragma unroll
        for (int v = 0; v < 4; v++) acc[t][v] = 0.f;

    for (int chunk = 0; chunk < 16; chunk++) {
        const float4* xs = (const float4*)(Xg + (size_t)chunk * 64 * D);
#pragma unroll
        for (int q = 0; q < 8; q++) {
            int idx = tid + 256 * q;
            int row = idx >> 5, c4 = idx & 31;
            float4 f = xs[idx];
            uint32_t h01, l01, h23, l23;
            split2(f.x, f.y, h01, l01);
            split2(f.z, f.w, h23, l23);
            uint32_t off = (uint32_t)(row * GSROW + 4 * c4) * 2;
            *(uint2*)((char*)sXH + off) = make_uint2(h01, h23);
            *(uint2*)((char*)sXL + off) = make_uint2(l01, l23);
        }
        __syncthreads();

#pragma unroll
        for (int j = 0; j < 4; j++) {
            uint32_t aoff = ((j * 16 + arl) * GSROW + acol) * 2;
            uint32_t ah[4], al[4];
            ldsm4t(ah, sbh + aoff);
            ldsm4t(al, sbl + aoff);
#pragma unroll
            for (int tp = 0; tp < 8; tp++) {
                uint32_t boff = ((j * 16 + brl) * GSROW + (2 * tp + bct) * 8) * 2;
                uint32_t bh[4];
                ldsm4t(bh, sbh + boff);
                mma16816(acc[2 * tp],     ah, bh);
                mma16816(acc[2 * tp],     al, bh);
                mma16816(acc[2 * tp + 1], ah, bh + 2);
                mma16816(acc[2 * tp + 1], al, bh + 2);
            }
        }
        __syncthreads();
    }

    float* G = g_grams + ((size_t)split * NGRAPH + graph) * D * D;
    const int ra = lane >> 2;
    const int ca = (lane & 3) * 2;
#pragma unroll
    for (int t = 0; t < 16; t++) {
        int col = t * 8 + ca;
        *(float2*)&G[(m0 + ra) * D + col]     = make_float2(acc[t][0], acc[t][1]);
        *(float2*)&G[(m0 + ra + 8) * D + col] = make_float2(acc[t][2], acc[t][3]);
    }
}

// ---------------------------------------------------------------------------
// HMMA fused match kernel (fp16). 2048 blocks x 256 threads, 64 rows/block.
// Phase1: Y = X*G (3-pass). Products (one loop): p_num hi/lo, p_n1 hi, p_n2 hi
// with ys = y * 2^-6 (exact; cosine is scale-invariant in y).
// Phase2 (merged): num = Pn*W (3-pass), n1 = P1*W (1-pass), n2 = P2*W (1-pass).
// ---------------------------------------------------------------------------
#define SROW    136
#define OFF_XH  0u
#define OFF_XL  17408u
#define OFF_BH  34816u
#define OFF_BL  69632u
#define OFF_PNH 104448u
#define OFF_PNL 121856u
#define OFF_P1H 139264u
#define OFF_P2H 156672u
#define SMEM_NEED 174080

__global__ __launch_bounds__(256) void match_mma_kernel(
    const float* __restrict__ feats, float* __restrict__ out) {
    extern __shared__ __align__(16) char smem[];
    const uint32_t sb = smem_to_u32(smem);

    const int tid  = threadIdx.x;
    const int w    = tid >> 5;
    const int lane = tid & 31;
    const int mt   = w >> 1;
    const int nh   = w & 1;
    const int r0   = blockIdx.x * 64;
    const int gi   = r0 >> 11;

    const uint32_t* ghp = (const uint32_t*)(g_gh + (size_t)(gi ^ 1) * D * D);
    const uint32_t* glp = (const uint32_t*)(g_gl + (size_t)(gi ^ 1) * D * D);
    const uint32_t* whp = (const uint32_t*)g_wh;
    const uint32_t* wlp = (const uint32_t*)g_wl;

    // ---- stage X (split hi/lo) ----
    {
        const float4* xs = (const float4*)(feats + (size_t)r0 * D);
#pragma unroll
        for (int q = 0; q < 8; q++) {
            int idx = tid + 256 * q;
            int row = idx >> 5, c4 = idx & 31;
            float4 f = xs[idx];
            uint32_t h01, l01, h23, l23;
            split2(f.x, f.y, h01, l01);
            split2(f.z, f.w, h23, l23);
            uint32_t off = (uint32_t)(row * SROW + 4 * c4) * 2;
            *(uint2*)(smem + OFF_XH + off) = make_uint2(h01, h23);
            *(uint2*)(smem + OFF_XL + off) = make_uint2(l01, l23);
        }
    }
    // ---- stage G hi/lo ----
#pragma unroll
    for (int q = 0; q < 32; q++) {
        int idx = tid + 256 * q;
        int row = idx >> 6, cp = idx & 63;
        uint32_t off = (uint32_t)(row * SROW + 2 * cp) * 2;
        *(uint32_t*)(smem + OFF_BH + off) = ghp[idx];
        *(uint32_t*)(smem + OFF_BL + off) = glp[idx];
    }
    __syncthreads();

    // fragment lane offsets
    const uint32_t arow = mt * 16 + (lane & 7) + ((lane >> 3) & 1) * 8;
    const uint32_t acolh = (lane >> 4) * 8;
    const int g    = lane >> 3;
    const uint32_t bnrow = (uint32_t)((g >> 1) * 8 + (lane & 7));
    const uint32_t bkoff = (uint32_t)((g & 1) * 8);

    // ---------------- Phase 1: Y = X * G (3-pass) ----------------
    float accY[8][4];
#pragma unroll
    for (int t = 0; t < 8; t++)
#pragma unroll
        for (int v = 0; v < 4; v++) accY[t][v] = 0.f;

#pragma unroll
    for (int j = 0; j < 8; j++) {
        uint32_t aoff = (arow * SROW + j * 16 + acolh) * 2;
        uint32_t ah[4], al[4];
        ldsm4(ah, sb + OFF_XH + aoff);
        ldsm4(al, sb + OFF_XL + aoff);
#pragma unroll
        for (int tp = 0; tp < 4; tp++) {
            uint32_t boff = (((uint32_t)(nh * 64 + tp * 16) + bnrow) * SROW + j * 16 + bkoff) * 2;
            uint32_t bh[4], bl2[4];
            ldsm4(bh,  sb + OFF_BH + boff);
            ldsm4(bl2, sb + OFF_BL + boff);
            mma16816(accY[2 * tp], ah, bh);
            mma16816(accY[2 * tp], al, bh);
            mma16816(accY[2 * tp], ah, bl2);
            mma16816(accY[2 * tp + 1], ah, bh + 2);
            mma16816(accY[2 * tp + 1], al, bh + 2);
            mma16816(accY[2 * tp + 1], ah, bl2 + 2);
        }
    }
    __syncthreads();   // done reading G; BH/BL can be overwritten

    // ---- stage W hi/lo (over G) ----
#pragma unroll
    for (int q = 0; q < 32; q++) {
        int idx = tid + 256 * q;
        int row = idx >> 6, cp = idx & 63;
        uint32_t off = (uint32_t)(row * SROW + 2 * cp) * 2;
        *(uint32_t*)(smem + OFF_BH + off) = whp[idx];
        *(uint32_t*)(smem + OFF_BL + off) = wlp[idx];
    }

    // ---- products (single loop): p_num hi/lo, p_n1 hi, p_n2 hi ----
    const int ra = lane >> 2;
    const int ca = (lane & 3) * 2;
#pragma unroll
    for (int t = 0; t < 8; t++) {
        int col = nh * 64 + t * 8 + ca;
#pragma unroll
        for (int h2 = 0; h2 < 2; h2++) {
            int row = mt * 16 + ra + 8 * h2;
            uint32_t off = (uint32_t)(row * SROW + col) * 2;
            float2 xh = __half22float2(*(const __half2*)(smem + OFF_XH + off));
            float2 xl = __half22float2(*(const __half2*)(smem + OFF_XL + off));
            float x0 = xh.x + xl.x;
            float x1 = xh.y + xl.y;
            float y0 = accY[t][2 * h2] * YSCALE;
            float y1 = accY[t][2 * h2 + 1] * YSCALE;

            uint32_t ph, pl;
            split2(x0 * y0, x1 * y1, ph, pl);
            *(uint32_t*)(smem + OFF_PNH + off) = ph;
            *(uint32_t*)(smem + OFF_PNL + off) = pl;
            *(uint32_t*)(smem + OFF_P1H + off) = h2u(__floats2half2_rn(x0 * x0, x1 * x1));
            *(uint32_t*)(smem + OFF_P2H + off) = h2u(__floats2half2_rn(y0 * y0, y1 * y1));
        }
    }
    __syncthreads();

    // ---------------- Phase 2 (merged): num 3-pass, n1 1-pass, n2 1-pass ----
    float accN[8][4], accB[8][4], accC[8][4];
#pragma unroll
    for (int t = 0; t < 8; t++)
#pragma unroll
        for (int v = 0; v < 4; v++) { accN[t][v] = 0.f; accB[t][v] = 0.f; accC[t][v] = 0.f; }

#pragma unroll
    for (int j = 0; j < 8; j++) {
        uint32_t aoff = (arow * SROW + j * 16 + acolh) * 2;
        uint32_t n_h[4], n_l[4], p1[4], p2[4];
        ldsm4(n_h, sb + OFF_PNH + aoff);
        ldsm4(n_l, sb + OFF_PNL + aoff);
        ldsm4(p1,  sb + OFF_P1H + aoff);
        ldsm4(p2,  sb + OFF_P2H + aoff);
#pragma unroll
        for (int tp = 0; tp < 4; tp++) {
            uint32_t boff = (((uint32_t)(nh * 64 + tp * 16) + bnrow) * SROW + j * 16 + bkoff) * 2;
            uint32_t wh_[4], wl_[4];
            ldsm4(wh_, sb + OFF_BH + boff);
            ldsm4(wl_, sb + OFF_BL + boff);
            mma16816(accN[2 * tp], n_h, wh_);
            mma16816(accN[2 * tp], n_l, wh_);
            mma16816(accN[2 * tp], n_h, wl_);
            mma16816(accB[2 * tp], p1, wh_);
            mma16816(accC[2 * tp], p2, wh_);
            mma16816(accN[2 * tp + 1], n_h, wh_ + 2);
            mma16816(accN[2 * tp + 1], n_l, wh_ + 2);
            mma16816(accN[2 * tp + 1], n_h, wl_ + 2);
            mma16816(accB[2 * tp + 1], p1, wh_ + 2);
            mma16816(accC[2 * tp + 1], p2, wh_ + 2);
        }
    }

    // ---------------- Epilogue ----------------
#pragma unroll
    for (int t = 0; t < 8; t++) {
        int col = nh * 64 + t * 8 + ca;
#pragma unroll
        for (int h2 = 0; h2 < 2; h2++) {
            int row = r0 + mt * 16 + ra + 8 * h2;
            float n0v = accN[t][2 * h2], n1v = accN[t][2 * h2 + 1];
            float b0v = accB[t][2 * h2], b1v = accB[t][2 * h2 + 1];
            float c0v = accC[t][2 * h2], c1v = accC[t][2 * h2 + 1];
            float2 o;
            o.x = n0v / fmaxf(sqrtf(b0v * c0v), EPS);
            o.y = n1v / fmaxf(sqrtf(b1v * c1v), EPS);
            *(float2*)(out + (size_t)row * D + col) = o;
        }
    }
}

// ---------------------------------------------------------------------------
extern "C" void kernel_launch(void* const* d_in, const int* in_sizes, int n_in,
                              void* d_out, int out_size) {
    const float* feats = (const float*)d_in[0];
    const float* mp_w  = (const float*)d_in[1];
    float* out = (float*)d_out;

    static bool attr_done = false;
    if (!attr_done) {
        cudaFuncSetAttribute(match_mma_kernel,
                             cudaFuncAttributeMaxDynamicSharedMemorySize, SMEM_NEED);
        attr_done = true;
    }

    int N = in_sizes[0] / D;   // 131072 rows

    wcvt_kernel<<<(D * D + 255) / 256, 256>>>(mp_w);
    gram_mma_kernel<<<NGRAPH * 2, 256>>>(feats);
    gram_cvt_kernel<<<(NGRAPH * D * D / 4 + 255) / 256, 256>>>();
    match_mma_kernel<<<N / 64, 256, SMEM_NEED>>>(feats, out);
}

// round 7
// speedup vs baseline: 3.8585x; 1.0012x over previous
#include <cuda_runtime.h>
#include <cuda_fp16.h>
#include <math.h>
#include <stdint.h>

#define D      128
#define NGRAPH 64
#define LROWS  2048
#define EPS    1e-8f
#define YSCALE 0.015625f   // 2^-6, exact

// ---------------------------------------------------------------------------
// Global scratch
// ---------------------------------------------------------------------------
__device__ float  g_grams[2 * NGRAPH * D * D];   // two split-K partials
__device__ __half g_gh[NGRAPH * D * D];
__device__ __half g_gl[NGRAPH * D * D];
__device__ __half g_wh[D * D];
__device__ __half g_wl[D * D];

// ---------------------------------------------------------------------------
// Helpers
// ---------------------------------------------------------------------------
__device__ __forceinline__ uint32_t smem_to_u32(const void* p) {
    uint32_t a;
    asm("{ .reg .u64 t; cvta.to.shared.u64 t, %1; cvt.u32.u64 %0, t; }" : "=r"(a) : "l"(p));
    return a;
}
__device__ __forceinline__ uint32_t h2u(__half2 h) { return *(uint32_t*)&h; }

__device__ __forceinline__ void ldsm4(uint32_t* r, uint32_t addr) {
    asm volatile("ldmatrix.sync.aligned.m8n8.x4.shared.b16 {%0,%1,%2,%3}, [%4];"
        : "=r"(r[0]), "=r"(r[1]), "=r"(r[2]), "=r"(r[3]) : "r"(addr));
}
__device__ __forceinline__ void ldsm4t(uint32_t* r, uint32_t addr) {
    asm volatile("ldmatrix.sync.aligned.m8n8.x4.trans.shared.b16 {%0,%1,%2,%3}, [%4];"
        : "=r"(r[0]), "=r"(r[1]), "=r"(r[2]), "=r"(r[3]) : "r"(addr));
}
__device__ __forceinline__ void mma16816(float* c, const uint32_t* a, const uint32_t* b) {
    asm volatile("mma.sync.aligned.m16n8k16.row.col.f32.f16.f16.f32 "
        "{%0,%1,%2,%3}, {%4,%5,%6,%7}, {%8,%9}, {%0,%1,%2,%3};"
        : "+f"(c[0]), "+f"(c[1]), "+f"(c[2]), "+f"(c[3])
        : "r"(a[0]), "r"(a[1]), "r"(a[2]), "r"(a[3]), "r"(b[0]), "r"(b[1]));
}

// split a,b -> (hi half2, lo half2)
__device__ __forceinline__ void split2(float a, float b, uint32_t& hi, uint32_t& lo) {
    __half2 h = __floats2half2_rn(a, b);
    float2 hf = __half22float2(h);
    __half2 l = __floats2half2_rn(a - hf.x, b - hf.y);
    hi = h2u(h); lo = h2u(l);
}

// ---------------------------------------------------------------------------
__global__ void wcvt_kernel(const float* __restrict__ mp_w) {
    int idx = blockIdx.x * blockDim.x + threadIdx.x;
    if (idx >= D * D) return;
    float v = mp_w[idx];
    float w2 = v * v;
    __half h = __float2half_rn(w2);
    g_wh[idx] = h;
    g_wl[idx] = __float2half_rn(w2 - __half2float(h));
}

__global__ void gram_cvt_kernel() {
    int idx = blockIdx.x * blockDim.x + threadIdx.x;
    if (idx >= NGRAPH * D * D / 4) return;
    float4 a = *(const float4*)(g_grams + 4 * (size_t)idx);
    float4 b = *(const float4*)(g_grams + NGRAPH * D * D + 4 * (size_t)idx);
    float4 v = make_float4(a.x + b.x, a.y + b.y, a.z + b.z, a.w + b.w);
    uint32_t h01, l01, h23, l23;
    split2(v.x, v.y, h01, l01);
    split2(v.z, v.w, h23, l23);
    *(uint2*)(g_gh + 4 * (size_t)idx) = make_uint2(h01, h23);
    *(uint2*)(g_gl + 4 * (size_t)idx) = make_uint2(l01, l23);
}

// ---------------------------------------------------------------------------
// HMMA Gram kernel (fp16, 2-pass): G[g] = X_g^T X_g. 128 blocks, K=1024 each.
// ---------------------------------------------------------------------------
#define GSROW 136

__global__ __launch_bounds__(256) void gram_mma_kernel(const float* __restrict__ feats) {
    __shared__ __half sXH[64 * GSROW];
    __shared__ __half sXL[64 * GSROW];
    const uint32_t sbh = smem_to_u32(sXH);
    const uint32_t sbl = smem_to_u32(sXL);

    const int tid  = threadIdx.x;
    const int w    = tid >> 5;
    const int lane = tid & 31;
    const int graph = blockIdx.x >> 1;
    const int split = blockIdx.x & 1;
    const int m0   = w * 16;

    const float* Xg = feats + ((size_t)graph * LROWS + (size_t)split * 1024) * D;

    const int g   = lane >> 3;
    const int li  = lane & 7;
    const uint32_t arl  = (uint32_t)((g >> 1) * 8 + li);
    const uint32_t acol = (uint32_t)(m0 + (g & 1) * 8);
    const uint32_t brl  = (uint32_t)((g & 1) * 8 + li);
    const uint32_t bct  = (uint32_t)(g >> 1);

    float acc[16][4];
#pragma unroll
    for (int t = 0; t < 16; t++)
#pragma unroll
        for (int v = 0; v < 4; v++) acc[t][v] = 0.f;

    for (int chunk = 0; chunk < 16; chunk++) {
        const float4* xs = (const float4*)(Xg + (size_t)chunk * 64 * D);
#pragma unroll
        for (int q = 0; q < 8; q++) {
            int idx = tid + 256 * q;
            int row = idx >> 5, c4 = idx & 31;
            float4 f = xs[idx];
            uint32_t h01, l01, h23, l23;
            split2(f.x, f.y, h01, l01);
            split2(f.z, f.w, h23, l23);
            uint32_t off = (uint32_t)(row * GSROW + 4 * c4) * 2;
            *(uint2*)((char*)sXH + off) = make_uint2(h01, h23);
            *(uint2*)((char*)sXL + off) = make_uint2(l01, l23);
        }
        __syncthreads();

#pragma unroll
        for (int j = 0; j < 4; j++) {
            uint32_t aoff = ((j * 16 + arl) * GSROW + acol) * 2;
            uint32_t ah[4], al[4];
            ldsm4t(ah, sbh + aoff);
            ldsm4t(al, sbl + aoff);
#pragma unroll
            for (int tp = 0; tp < 8; tp++) {
                uint32_t boff = ((j * 16 + brl) * GSROW + (2 * tp + bct) * 8) * 2;
                uint32_t bh[4];
                ldsm4t(bh, sbh + boff);
                mma16816(acc[2 * tp],     ah, bh);
                mma16816(acc[2 * tp],     al, bh);
                mma16816(acc[2 * tp + 1], ah, bh + 2);
                mma16816(acc[2 * tp + 1], al, bh + 2);
            }
        }
        __syncthreads();
    }

    float* G = g_grams + ((size_t)split * NGRAPH + graph) * D * D;
    const int ra = lane >> 2;
    const int ca = (lane & 3) * 2;
#pragma unroll
    for (int t = 0; t < 16; t++) {
        int col = t * 8 + ca;
        *(float2*)&G[(m0 + ra) * D + col]     = make_float2(acc[t][0], acc[t][1]);
        *(float2*)&G[(m0 + ra + 8) * D + col] = make_float2(acc[t][2], acc[t][3]);
    }
}

// ---------------------------------------------------------------------------
// HMMA fused match kernel (fp16), 32 rows/block, 128 threads, 2 blocks/SM.
// Warp w: mt = w>>1 (m16 tile 0..1), nh = w&1 (64-col half).
// num products overwrite X hi/lo IN PLACE (same thread, same offsets).
// Phase2 (merged): num = Pn*W (3-pass), n1 (1-pass), n2 (1-pass).
// smem = 102KB -> 2 blocks/SM so one block's MMAs overlap the other's
// staging/products/epilogue.
// ---------------------------------------------------------------------------
#define SROW    136
#define OFF_XH  0u          //  8704 B  (32 x 136 halves) -> PN hi after products
#define OFF_XL  8704u       //  8704 B                    -> PN lo after products
#define OFF_BH  17408u      // 34816 B  (G hi, then W hi)
#define OFF_BL  52224u      // 34816 B  (G lo, then W lo)
#define OFF_P1H 87040u      //  8704 B
#define OFF_P2H 95744u      //  8704 B
#define SMEM_NEED 104448

__global__ __launch_bounds__(128, 2) void match_mma_kernel(
    const float* __restrict__ feats, float* __restrict__ out) {
    extern __shared__ __align__(16) char smem[];
    const uint32_t sb = smem_to_u32(smem);

    const int tid  = threadIdx.x;
    const int w    = tid >> 5;
    const int lane = tid & 31;
    const int mt   = w >> 1;       // m16 tile 0..1
    const int nh   = w & 1;        // n half
    const int r0   = blockIdx.x * 32;
    const int gi   = r0 >> 11;

    const uint2* ghp = (const uint2*)(g_gh + (size_t)(gi ^ 1) * D * D);
    const uint2* glp = (const uint2*)(g_gl + (size_t)(gi ^ 1) * D * D);
    const uint2* whp = (const uint2*)g_wh;
    const uint2* wlp = (const uint2*)g_wl;

    // ---- stage X (split hi/lo): 1024 float4, 8 per thread ----
    {
        const float4* xs = (const float4*)(feats + (size_t)r0 * D);
#pragma unroll
        for (int q = 0; q < 8; q++) {
            int idx = tid + 128 * q;
            int row = idx >> 5, c4 = idx & 31;
            float4 f = xs[idx];
            uint32_t h01, l01, h23, l23;
            split2(f.x, f.y, h01, l01);
            split2(f.z, f.w, h23, l23);
            uint32_t off = (uint32_t)(row * SROW + 4 * c4) * 2;
            *(uint2*)(smem + OFF_XH + off) = make_uint2(h01, h23);
            *(uint2*)(smem + OFF_XL + off) = make_uint2(l01, l23);
        }
    }
    // ---- stage G hi/lo: 4096 uint2 per buffer, 32 per thread ----
#pragma unroll
    for (int q = 0; q < 32; q++) {
        int pi = tid + 128 * q;
        int row = pi >> 5, cp2 = pi & 31;
        uint32_t off = (uint32_t)(row * SROW + 4 * cp2) * 2;
        *(uint2*)(smem + OFF_BH + off) = ghp[pi];
        *(uint2*)(smem + OFF_BL + off) = glp[pi];
    }
    __syncthreads();

    // fragment lane offsets
    const uint32_t arow = mt * 16 + (lane & 7) + ((lane >> 3) & 1) * 8;
    const uint32_t acolh = (lane >> 4) * 8;
    const int g    = lane >> 3;
    const uint32_t bnrow = (uint32_t)((g >> 1) * 8 + (lane & 7));
    const uint32_t bkoff = (uint32_t)((g & 1) * 8);

    // ---------------- Phase 1: Y = X * G (3-pass) ----------------
    float accY[8][4];
#pragma unroll
    for (int t = 0; t < 8; t++)
#pragma unroll
        for (int v = 0; v < 4; v++) accY[t][v] = 0.f;

#pragma unroll
    for (int j = 0; j < 8; j++) {
        uint32_t aoff = (arow * SROW + j * 16 + acolh) * 2;
        uint32_t ah[4], al[4];
        ldsm4(ah, sb + OFF_XH + aoff);
        ldsm4(al, sb + OFF_XL + aoff);
#pragma unroll
        for (int tp = 0; tp < 4; tp++) {
            uint32_t boff = (((uint32_t)(nh * 64 + tp * 16) + bnrow) * SROW + j * 16 + bkoff) * 2;
            uint32_t bh[4], bl2[4];
            ldsm4(bh,  sb + OFF_BH + boff);
            ldsm4(bl2, sb + OFF_BL + boff);
            mma16816(accY[2 * tp], ah, bh);
            mma16816(accY[2 * tp], al, bh);
            mma16816(accY[2 * tp], ah, bl2);
            mma16816(accY[2 * tp + 1], ah, bh + 2);
            mma16816(accY[2 * tp + 1], al, bh + 2);
            mma16816(accY[2 * tp + 1], ah, bl2 + 2);
        }
    }
    __syncthreads();   // done reading G + X fragments; BH/BL and X writable

    // ---- stage W hi/lo (over G) ----
#pragma unroll
    for (int q = 0; q < 32; q++) {
        int pi = tid + 128 * q;
        int row = pi >> 5, cp2 = pi & 31;
        uint32_t off = (uint32_t)(row * SROW + 4 * cp2) * 2;
        *(uint2*)(smem + OFF_BH + off) = whp[pi];
        *(uint2*)(smem + OFF_BL + off) = wlp[pi];
    }

    // ---- products: read x, write PN hi/lo IN PLACE into XH/XL; p1,p2 hi ----
    const int ra = lane >> 2;
    const int ca = (lane & 3) * 2;
#pragma unroll
    for (int t = 0; t < 8; t++) {
        int col = nh * 64 + t * 8 + ca;
#pragma unroll
        for (int h2 = 0; h2 < 2; h2++) {
            int row = mt * 16 + ra + 8 * h2;
            uint32_t off = (uint32_t)(row * SROW + col) * 2;
            float2 xh = __half22float2(*(const __half2*)(smem + OFF_XH + off));
            float2 xl = __half22float2(*(const __half2*)(smem + OFF_XL + off));
            float x0 = xh.x + xl.x;
            float x1 = xh.y + xl.y;
            float y0 = accY[t][2 * h2] * YSCALE;
            float y1 = accY[t][2 * h2 + 1] * YSCALE;

            uint32_t ph, pl;
            split2(x0 * y0, x1 * y1, ph, pl);
            *(uint32_t*)(smem + OFF_XH + off) = ph;   // PN hi (in place)
            *(uint32_t*)(smem + OFF_XL + off) = pl;   // PN lo (in place)
            *(uint32_t*)(smem + OFF_P1H + off) = h2u(__floats2half2_rn(x0 * x0, x1 * x1));
            *(uint32_t*)(smem + OFF_P2H + off) = h2u(__floats2half2_rn(y0 * y0, y1 * y1));
        }
    }
    __syncthreads();

    // ---------------- Phase 2 (merged): num 3-pass, n1 1-pass, n2 1-pass ----
    float accN[8][4], accB[8][4], accC[8][4];
#pragma unroll
    for (int t = 0; t < 8; t++)
#pragma unroll
        for (int v = 0; v < 4; v++) { accN[t][v] = 0.f; accB[t][v] = 0.f; accC[t][v] = 0.f; }

#pragma unroll
    for (int j = 0; j < 8; j++) {
        uint32_t aoff = (arow * SROW + j * 16 + acolh) * 2;
        uint32_t n_h[4], n_l[4], p1[4], p2[4];
        ldsm4(n_h, sb + OFF_XH + aoff);
        ldsm4(n_l, sb + OFF_XL + aoff);
        ldsm4(p1,  sb + OFF_P1H + aoff);
        ldsm4(p2,  sb + OFF_P2H + aoff);
#pragma unroll
        for (int tp = 0; tp < 4; tp++) {
            uint32_t boff = (((uint32_t)(nh * 64 + tp * 16) + bnrow) * SROW + j * 16 + bkoff) * 2;
            uint32_t wh_[4], wl_[4];
            ldsm4(wh_, sb + OFF_BH + boff);
            ldsm4(wl_, sb + OFF_BL + boff);
            mma16816(accN[2 * tp], n_h, wh_);
            mma16816(accN[2 * tp], n_l, wh_);
            mma16816(accN[2 * tp], n_h, wl_);
            mma16816(accB[2 * tp], p1, wh_);
            mma16816(accC[2 * tp], p2, wh_);
            mma16816(accN[2 * tp + 1], n_h, wh_ + 2);
            mma16816(accN[2 * tp + 1], n_l, wh_ + 2);
            mma16816(accN[2 * tp + 1], n_h, wl_ + 2);
            mma16816(accB[2 * tp + 1], p1, wh_ + 2);
            mma16816(accC[2 * tp + 1], p2, wh_ + 2);
        }
    }

    // ---------------- Epilogue ----------------
#pragma unroll
    for (int t = 0; t < 8; t++) {
        int col = nh * 64 + t * 8 + ca;
#pragma unroll
        for (int h2 = 0; h2 < 2; h2++) {
            int row = r0 + mt * 16 + ra + 8 * h2;
            float n0v = accN[t][2 * h2], n1v = accN[t][2 * h2 + 1];
            float b0v = accB[t][2 * h2], b1v = accB[t][2 * h2 + 1];
            float c0v = accC[t][2 * h2], c1v = accC[t][2 * h2 + 1];
            float2 o;
            o.x = n0v / fmaxf(sqrtf(b0v * c0v), EPS);
            o.y = n1v / fmaxf(sqrtf(b1v * c1v), EPS);
            *(float2*)(out + (size_t)row * D + col) = o;
        }
    }
}

// ---------------------------------------------------------------------------
extern "C" void kernel_launch(void* const* d_in, const int* in_sizes, int n_in,
                              void* d_out, int out_size) {
    const float* feats = (const float*)d_in[0];
    const float* mp_w  = (const float*)d_in[1];
    float* out = (float*)d_out;

    static bool attr_done = false;
    if (!attr_done) {
        cudaFuncSetAttribute(match_mma_kernel,
                             cudaFuncAttributeMaxDynamicSharedMemorySize, SMEM_NEED);
        attr_done = true;
    }

    int N = in_sizes[0] / D;   // 131072 rows

    wcvt_kernel<<<(D * D + 255) / 256, 256>>>(mp_w);
    gram_mma_kernel<<<NGRAPH * 2, 256>>>(feats);
    gram_cvt_kernel<<<(NGRAPH * D * D / 4 + 255) / 256, 256>>>();
    match_mma_kernel<<<N / 32, 128, SMEM_NEED>>>(feats, out);
}

// round 8
// speedup vs baseline: 4.0397x; 1.0470x over previous
#include <cuda_runtime.h>
#include <cuda_fp16.h>
#include <math.h>
#include <stdint.h>

#define D      128
#define NGRAPH 64
#define LROWS  2048
#define EPS    1e-8f
#define YSCALE 0.015625f   // 2^-6, exact

// ---------------------------------------------------------------------------
// Global scratch
// ---------------------------------------------------------------------------
__device__ float  g_grams[2 * NGRAPH * D * D];   // two split-K partials
__device__ __half g_gh[NGRAPH * D * D];
__device__ __half g_gl[NGRAPH * D * D];
__device__ __half g_wh[D * D];
__device__ __half g_wl[D * D];

// ---------------------------------------------------------------------------
// Helpers
// ---------------------------------------------------------------------------
__device__ __forceinline__ uint32_t smem_to_u32(const void* p) {
    uint32_t a;
    asm("{ .reg .u64 t; cvta.to.shared.u64 t, %1; cvt.u32.u64 %0, t; }" : "=r"(a) : "l"(p));
    return a;
}
__device__ __forceinline__ uint32_t h2u(__half2 h) { return *(uint32_t*)&h; }

__device__ __forceinline__ void ldsm4(uint32_t* r, uint32_t addr) {
    asm volatile("ldmatrix.sync.aligned.m8n8.x4.shared.b16 {%0,%1,%2,%3}, [%4];"
        : "=r"(r[0]), "=r"(r[1]), "=r"(r[2]), "=r"(r[3]) : "r"(addr));
}
__device__ __forceinline__ void ldsm4t(uint32_t* r, uint32_t addr) {
    asm volatile("ldmatrix.sync.aligned.m8n8.x4.trans.shared.b16 {%0,%1,%2,%3}, [%4];"
        : "=r"(r[0]), "=r"(r[1]), "=r"(r[2]), "=r"(r[3]) : "r"(addr));
}
__device__ __forceinline__ void mma16816(float* c, const uint32_t* a, const uint32_t* b) {
    asm volatile("mma.sync.aligned.m16n8k16.row.col.f32.f16.f16.f32 "
        "{%0,%1,%2,%3}, {%4,%5,%6,%7}, {%8,%9}, {%0,%1,%2,%3};"
        : "+f"(c[0]), "+f"(c[1]), "+f"(c[2]), "+f"(c[3])
        : "r"(a[0]), "r"(a[1]), "r"(a[2]), "r"(a[3]), "r"(b[0]), "r"(b[1]));
}

// split a,b -> (hi half2, lo half2)
__device__ __forceinline__ void split2(float a, float b, uint32_t& hi, uint32_t& lo) {
    __half2 h = __floats2half2_rn(a, b);
    float2 hf = __half22float2(h);
    __half2 l = __floats2half2_rn(a - hf.x, b - hf.y);
    hi = h2u(h); lo = h2u(l);
}

// ---------------------------------------------------------------------------
__global__ void wcvt_kernel(const float* __restrict__ mp_w) {
    int idx = blockIdx.x * blockDim.x + threadIdx.x;
    if (idx >= D * D) return;
    float v = mp_w[idx];
    float w2 = v * v;
    __half h = __float2half_rn(w2);
    g_wh[idx] = h;
    g_wl[idx] = __float2half_rn(w2 - __half2float(h));
}

__global__ void gram_cvt_kernel() {
    int idx = blockIdx.x * blockDim.x + threadIdx.x;
    if (idx >= NGRAPH * D * D / 4) return;
    float4 a = *(const float4*)(g_grams + 4 * (size_t)idx);
    float4 b = *(const float4*)(g_grams + NGRAPH * D * D + 4 * (size_t)idx);
    float4 v = make_float4(a.x + b.x, a.y + b.y, a.z + b.z, a.w + b.w);
    uint32_t h01, l01, h23, l23;
    split2(v.x, v.y, h01, l01);
    split2(v.z, v.w, h23, l23);
    *(uint2*)(g_gh + 4 * (size_t)idx) = make_uint2(h01, h23);
    *(uint2*)(g_gl + 4 * (size_t)idx) = make_uint2(l01, l23);
}

// ---------------------------------------------------------------------------
// HMMA Gram kernel (fp16, 2-pass): G[g] = X_g^T X_g. 128 blocks, K=1024 each.
// ---------------------------------------------------------------------------
#define GSROW 136

__global__ __launch_bounds__(256) void gram_mma_kernel(const float* __restrict__ feats) {
    __shared__ __half sXH[64 * GSROW];
    __shared__ __half sXL[64 * GSROW];
    const uint32_t sbh = smem_to_u32(sXH);
    const uint32_t sbl = smem_to_u32(sXL);

    const int tid  = threadIdx.x;
    const int w    = tid >> 5;
    const int lane = tid & 31;
    const int graph = blockIdx.x >> 1;
    const int split = blockIdx.x & 1;
    const int m0   = w * 16;

    const float* Xg = feats + ((size_t)graph * LROWS + (size_t)split * 1024) * D;

    const int g   = lane >> 3;
    const int li  = lane & 7;
    const uint32_t arl  = (uint32_t)((g >> 1) * 8 + li);
    const uint32_t acol = (uint32_t)(m0 + (g & 1) * 8);
    const uint32_t brl  = (uint32_t)((g & 1) * 8 + li);
    const uint32_t bct  = (uint32_t)(g >> 1);

    float acc[16][4];
#pragma unroll
    for (int t = 0; t < 16; t++)
#pragma unroll
        for (int v = 0; v < 4; v++) acc[t][v] = 0.f;

    for (int chunk = 0; chunk < 16; chunk++) {
        const float4* xs = (const float4*)(Xg + (size_t)chunk * 64 * D);
#pragma unroll
        for (int q = 0; q < 8; q++) {
            int idx = tid + 256 * q;
            int row = idx >> 5, c4 = idx & 31;
            float4 f = xs[idx];
            uint32_t h01, l01, h23, l23;
            split2(f.x, f.y, h01, l01);
            split2(f.z, f.w, h23, l23);
            uint32_t off = (uint32_t)(row * GSROW + 4 * c4) * 2;
            *(uint2*)((char*)sXH + off) = make_uint2(h01, h23);
            *(uint2*)((char*)sXL + off) = make_uint2(l01, l23);
        }
        __syncthreads();

#pragma unroll
        for (int j = 0; j < 4; j++) {
            uint32_t aoff = ((j * 16 + arl) * GSROW + acol) * 2;
            uint32_t ah[4], al[4];
            ldsm4t(ah, sbh + aoff);
            ldsm4t(al, sbl + aoff);
#pragma unroll
            for (int tp = 0; tp < 8; tp++) {
                uint32_t boff = ((j * 16 + brl) * GSROW + (2 * tp + bct) * 8) * 2;
                uint32_t bh[4];
                ldsm4t(bh, sbh + boff);
                mma16816(acc[2 * tp],     ah, bh);
                mma16816(acc[2 * tp],     al, bh);
                mma16816(acc[2 * tp + 1], ah, bh + 2);
                mma16816(acc[2 * tp + 1], al, bh + 2);
            }
        }
        __syncthreads();
    }

    float* G = g_grams + ((size_t)split * NGRAPH + graph) * D * D;
    const int ra = lane >> 2;
    const int ca = (lane & 3) * 2;
#pragma unroll
    for (int t = 0; t < 16; t++) {
        int col = t * 8 + ca;
        *(float2*)&G[(m0 + ra) * D + col]     = make_float2(acc[t][0], acc[t][1]);
        *(float2*)&G[(m0 + ra + 8) * D + col] = make_float2(acc[t][2], acc[t][3]);
    }
}

// ---------------------------------------------------------------------------
// HMMA fused match kernel (fp16): 32 rows/block, 256 threads (8 warps),
// 2 blocks/SM = 16 warps/SM. Warp w: mt = w>>2 (m16 tile 0..1),
// nq = w&3 (32-col quarter). Per-warp C-tile m16n32 -> 48 acc floats.
// num products overwrite X hi/lo IN PLACE (same thread, same offsets).
// ---------------------------------------------------------------------------
#define SROW    136
#define OFF_XH  0u          //  8704 B  -> PN hi after products
#define OFF_XL  8704u       //  8704 B  -> PN lo after products
#define OFF_BH  17408u      // 34816 B  (G hi, then W hi)
#define OFF_BL  52224u      // 34816 B  (G lo, then W lo)
#define OFF_P1H 87040u      //  8704 B
#define OFF_P2H 95744u      //  8704 B
#define SMEM_NEED 104448

__global__ __launch_bounds__(256, 2) void match_mma_kernel(
    const float* __restrict__ feats, float* __restrict__ out) {
    extern __shared__ __align__(16) char smem[];
    const uint32_t sb = smem_to_u32(smem);

    const int tid  = threadIdx.x;
    const int w    = tid >> 5;
    const int lane = tid & 31;
    const int mt   = w >> 2;       // m16 tile 0..1
    const int nq   = w & 3;        // n quarter (32 cols)
    const int r0   = blockIdx.x * 32;
    const int gi   = r0 >> 11;

    const uint2* ghp = (const uint2*)(g_gh + (size_t)(gi ^ 1) * D * D);
    const uint2* glp = (const uint2*)(g_gl + (size_t)(gi ^ 1) * D * D);
    const uint2* whp = (const uint2*)g_wh;
    const uint2* wlp = (const uint2*)g_wl;

    // ---- stage X (split hi/lo): 1024 float4, 4 per thread ----
    {
        const float4* xs = (const float4*)(feats + (size_t)r0 * D);
#pragma unroll
        for (int q = 0; q < 4; q++) {
            int idx = tid + 256 * q;
            int row = idx >> 5, c4 = idx & 31;
            float4 f = xs[idx];
            uint32_t h01, l01, h23, l23;
            split2(f.x, f.y, h01, l01);
            split2(f.z, f.w, h23, l23);
            uint32_t off = (uint32_t)(row * SROW + 4 * c4) * 2;
            *(uint2*)(smem + OFF_XH + off) = make_uint2(h01, h23);
            *(uint2*)(smem + OFF_XL + off) = make_uint2(l01, l23);
        }
    }
    // ---- stage G hi/lo: 4096 uint2 per buffer, 16 per thread ----
#pragma unroll
    for (int q = 0; q < 16; q++) {
        int pi = tid + 256 * q;
        int row = pi >> 5, cp2 = pi & 31;
        uint32_t off = (uint32_t)(row * SROW + 4 * cp2) * 2;
        *(uint2*)(smem + OFF_BH + off) = ghp[pi];
        *(uint2*)(smem + OFF_BL + off) = glp[pi];
    }
    __syncthreads();

    // fragment lane offsets
    const uint32_t arow = mt * 16 + (lane & 7) + ((lane >> 3) & 1) * 8;
    const uint32_t acolh = (lane >> 4) * 8;
    const int g    = lane >> 3;
    const uint32_t bnrow = (uint32_t)((g >> 1) * 8 + (lane & 7));
    const uint32_t bkoff = (uint32_t)((g & 1) * 8);

    // ---------------- Phase 1: Y = X * G (3-pass) ----------------
    float accY[4][4];
#pragma unroll
    for (int t = 0; t < 4; t++)
#pragma unroll
        for (int v = 0; v < 4; v++) accY[t][v] = 0.f;

#pragma unroll
    for (int j = 0; j < 8; j++) {
        uint32_t aoff = (arow * SROW + j * 16 + acolh) * 2;
        uint32_t ah[4], al[4];
        ldsm4(ah, sb + OFF_XH + aoff);
        ldsm4(al, sb + OFF_XL + aoff);
#pragma unroll
        for (int tp = 0; tp < 2; tp++) {
            uint32_t boff = (((uint32_t)(nq * 32 + tp * 16) + bnrow) * SROW + j * 16 + bkoff) * 2;
            uint32_t bh[4], bl2[4];
            ldsm4(bh,  sb + OFF_BH + boff);
            ldsm4(bl2, sb + OFF_BL + boff);
            mma16816(accY[2 * tp], ah, bh);
            mma16816(accY[2 * tp], al, bh);
            mma16816(accY[2 * tp], ah, bl2);
            mma16816(accY[2 * tp + 1], ah, bh + 2);
            mma16816(accY[2 * tp + 1], al, bh + 2);
            mma16816(accY[2 * tp + 1], ah, bl2 + 2);
        }
    }
    __syncthreads();   // done reading G + X fragments; BH/BL and X writable

    // ---- stage W hi/lo (over G) ----
#pragma unroll
    for (int q = 0; q < 16; q++) {
        int pi = tid + 256 * q;
        int row = pi >> 5, cp2 = pi & 31;
        uint32_t off = (uint32_t)(row * SROW + 4 * cp2) * 2;
        *(uint2*)(smem + OFF_BH + off) = whp[pi];
        *(uint2*)(smem + OFF_BL + off) = wlp[pi];
    }

    // ---- products: read x, write PN hi/lo IN PLACE into XH/XL; p1,p2 hi ----
    const int ra = lane >> 2;
    const int ca = (lane & 3) * 2;
#pragma unroll
    for (int t = 0; t < 4; t++) {
        int col = nq * 32 + t * 8 + ca;
#pragma unroll
        for (int h2 = 0; h2 < 2; h2++) {
            int row = mt * 16 + ra + 8 * h2;
            uint32_t off = (uint32_t)(row * SROW + col) * 2;
            float2 xh = __half22float2(*(const __half2*)(smem + OFF_XH + off));
            float2 xl = __half22float2(*(const __half2*)(smem + OFF_XL + off));
            float x0 = xh.x + xl.x;
            float x1 = xh.y + xl.y;
            float y0 = accY[t][2 * h2] * YSCALE;
            float y1 = accY[t][2 * h2 + 1] * YSCALE;

            uint32_t ph, pl;
            split2(x0 * y0, x1 * y1, ph, pl);
            *(uint32_t*)(smem + OFF_XH + off) = ph;   // PN hi (in place)
            *(uint32_t*)(smem + OFF_XL + off) = pl;   // PN lo (in place)
            *(uint32_t*)(smem + OFF_P1H + off) = h2u(__floats2half2_rn(x0 * x0, x1 * x1));
            *(uint32_t*)(smem + OFF_P2H + off) = h2u(__floats2half2_rn(y0 * y0, y1 * y1));
        }
    }
    __syncthreads();

    // ---------------- Phase 2 (merged): num 3-pass, n1 1-pass, n2 1-pass ----
    float accN[4][4], accB[4][4], accC[4][4];
#pragma unroll
    for (int t = 0; t < 4; t++)
#pragma unroll
        for (int v = 0; v < 4; v++) { accN[t][v] = 0.f; accB[t][v] = 0.f; accC[t][v] = 0.f; }

#pragma unroll
    for (int j = 0; j < 8; j++) {
        uint32_t aoff = (arow * SROW + j * 16 + acolh) * 2;
        uint32_t n_h[4], n_l[4], p1[4], p2[4];
        ldsm4(n_h, sb + OFF_XH + aoff);
        ldsm4(n_l, sb + OFF_XL + aoff);
        ldsm4(p1,  sb + OFF_P1H + aoff);
        ldsm4(p2,  sb + OFF_P2H + aoff);
#pragma unroll
        for (int tp = 0; tp < 2; tp++) {
            uint32_t boff = (((uint32_t)(nq * 32 + tp * 16) + bnrow) * SROW + j * 16 + bkoff) * 2;
            uint32_t wh_[4], wl_[4];
            ldsm4(wh_, sb + OFF_BH + boff);
            ldsm4(wl_, sb + OFF_BL + boff);
            mma16816(accN[2 * tp], n_h, wh_);
            mma16816(accN[2 * tp], n_l, wh_);
            mma16816(accN[2 * tp], n_h, wl_);
            mma16816(accB[2 * tp], p1, wh_);
            mma16816(accC[2 * tp], p2, wh_);
            mma16816(accN[2 * tp + 1], n_h, wh_ + 2);
            mma16816(accN[2 * tp + 1], n_l, wh_ + 2);
            mma16816(accN[2 * tp + 1], n_h, wl_ + 2);
            mma16816(accB[2 * tp + 1], p1, wh_ + 2);
            mma16816(accC[2 * tp + 1], p2, wh_ + 2);
        }
    }

    // ---------------- Epilogue ----------------
#pragma unroll
    for (int t = 0; t < 4; t++) {
        int col = nq * 32 + t * 8 + ca;
#pragma unroll
        for (int h2 = 0; h2 < 2; h2++) {
            int row = r0 + mt * 16 + ra + 8 * h2;
            float n0v = accN[t][2 * h2], n1v = accN[t][2 * h2 + 1];
            float b0v = accB[t][2 * h2], b1v = accB[t][2 * h2 + 1];
            float c0v = accC[t][2 * h2], c1v = accC[t][2 * h2 + 1];
            float2 o;
            o.x = n0v / fmaxf(sqrtf(b0v * c0v), EPS);
            o.y = n1v / fmaxf(sqrtf(b1v * c1v), EPS);
            *(float2*)(out + (size_t)row * D + col) = o;
        }
    }
}

// ---------------------------------------------------------------------------
extern "C" void kernel_launch(void* const* d_in, const int* in_sizes, int n_in,
                              void* d_out, int out_size) {
    const float* feats = (const float*)d_in[0];
    const float* mp_w  = (const float*)d_in[1];
    float* out = (float*)d_out;

    static bool attr_done = false;
    if (!attr_done) {
        cudaFuncSetAttribute(match_mma_kernel,
                             cudaFuncAttributeMaxDynamicSharedMemorySize, SMEM_NEED);
        attr_done = true;
    }

    int N = in_sizes[0] / D;   // 131072 rows

    wcvt_kernel<<<(D * D + 255) / 256, 256>>>(mp_w);
    gram_mma_kernel<<<NGRAPH * 2, 256>>>(feats);
    gram_cvt_kernel<<<(NGRAPH * D * D / 4 + 255) / 256, 256>>>();
    match_mma_kernel<<<N / 32, 256, SMEM_NEED>>>(feats, out);
}

// round 9
// speedup vs baseline: 4.0845x; 1.0111x over previous
#include <cuda_runtime.h>
#include <cuda_fp16.h>
#include <math.h>
#include <stdint.h>

#define D      128
#define NGRAPH 64
#define LROWS  2048
#define EPS    1e-8f
#define YSCALE 0.015625f   // 2^-6, exact

// ---------------------------------------------------------------------------
// Global scratch
// ---------------------------------------------------------------------------
__device__ float  g_grams[2 * NGRAPH * D * D];   // two split-K partials
__device__ __half g_gh[NGRAPH * D * D];
__device__ __half g_gl[NGRAPH * D * D];
__device__ __half g_wh[D * D];
__device__ __half g_wl[D * D];

// ---------------------------------------------------------------------------
// Helpers
// ---------------------------------------------------------------------------
__device__ __forceinline__ uint32_t smem_to_u32(const void* p) {
    uint32_t a;
    asm("{ .reg .u64 t; cvta.to.shared.u64 t, %1; cvt.u32.u64 %0, t; }" : "=r"(a) : "l"(p));
    return a;
}
__device__ __forceinline__ uint32_t h2u(__half2 h) { return *(uint32_t*)&h; }

__device__ __forceinline__ void ldsm4(uint32_t* r, uint32_t addr) {
    asm volatile("ldmatrix.sync.aligned.m8n8.x4.shared.b16 {%0,%1,%2,%3}, [%4];"
        : "=r"(r[0]), "=r"(r[1]), "=r"(r[2]), "=r"(r[3]) : "r"(addr));
}
__device__ __forceinline__ void ldsm4t(uint32_t* r, uint32_t addr) {
    asm volatile("ldmatrix.sync.aligned.m8n8.x4.trans.shared.b16 {%0,%1,%2,%3}, [%4];"
        : "=r"(r[0]), "=r"(r[1]), "=r"(r[2]), "=r"(r[3]) : "r"(addr));
}
__device__ __forceinline__ void stsm4(uint32_t addr, const uint32_t* r) {
    asm volatile("stmatrix.sync.aligned.m8n8.x4.shared.b16 [%0], {%1,%2,%3,%4};"
        :: "r"(addr), "r"(r[0]), "r"(r[1]), "r"(r[2]), "r"(r[3]) : "memory");
}
__device__ __forceinline__ void mma16816(float* c, const uint32_t* a, const uint32_t* b) {
    asm volatile("mma.sync.aligned.m16n8k16.row.col.f32.f16.f16.f32 "
        "{%0,%1,%2,%3}, {%4,%5,%6,%7}, {%8,%9}, {%0,%1,%2,%3};"
        : "+f"(c[0]), "+f"(c[1]), "+f"(c[2]), "+f"(c[3])
        : "r"(a[0]), "r"(a[1]), "r"(a[2]), "r"(a[3]), "r"(b[0]), "r"(b[1]));
}

// split a,b -> (hi half2, lo half2)
__device__ __forceinline__ void split2(float a, float b, uint32_t& hi, uint32_t& lo) {
    __half2 h = __floats2half2_rn(a, b);
    float2 hf = __half22float2(h);
    __half2 l = __floats2half2_rn(a - hf.x, b - hf.y);
    hi = h2u(h); lo = h2u(l);
}

// ---------------------------------------------------------------------------
__global__ void wcvt_kernel(const float* __restrict__ mp_w) {
    int idx = blockIdx.x * blockDim.x + threadIdx.x;
    if (idx >= D * D) return;
    float v = mp_w[idx];
    float w2 = v * v;
    __half h = __float2half_rn(w2);
    g_wh[idx] = h;
    g_wl[idx] = __float2half_rn(w2 - __half2float(h));
}

__global__ void gram_cvt_kernel() {
    int idx = blockIdx.x * blockDim.x + threadIdx.x;
    if (idx >= NGRAPH * D * D / 4) return;
    float4 a = *(const float4*)(g_grams + 4 * (size_t)idx);
    float4 b = *(const float4*)(g_grams + NGRAPH * D * D + 4 * (size_t)idx);
    float4 v = make_float4(a.x + b.x, a.y + b.y, a.z + b.z, a.w + b.w);
    uint32_t h01, l01, h23, l23;
    split2(v.x, v.y, h01, l01);
    split2(v.z, v.w, h23, l23);
    *(uint2*)(g_gh + 4 * (size_t)idx) = make_uint2(h01, h23);
    *(uint2*)(g_gl + 4 * (size_t)idx) = make_uint2(l01, l23);
}

// ---------------------------------------------------------------------------
// HMMA Gram kernel (fp16, 2-pass): G[g] = X_g^T X_g. 128 blocks, K=1024 each.
// ---------------------------------------------------------------------------
#define GSROW 136

__global__ __launch_bounds__(256) void gram_mma_kernel(const float* __restrict__ feats) {
    __shared__ __half sXH[64 * GSROW];
    __shared__ __half sXL[64 * GSROW];
    const uint32_t sbh = smem_to_u32(sXH);
    const uint32_t sbl = smem_to_u32(sXL);

    const int tid  = threadIdx.x;
    const int w    = tid >> 5;
    const int lane = tid & 31;
    const int graph = blockIdx.x >> 1;
    const int split = blockIdx.x & 1;
    const int m0   = w * 16;

    const float* Xg = feats + ((size_t)graph * LROWS + (size_t)split * 1024) * D;

    const int g   = lane >> 3;
    const int li  = lane & 7;
    const uint32_t arl  = (uint32_t)((g >> 1) * 8 + li);
    const uint32_t acol = (uint32_t)(m0 + (g & 1) * 8);
    const uint32_t brl  = (uint32_t)((g & 1) * 8 + li);
    const uint32_t bct  = (uint32_t)(g >> 1);

    float acc[16][4];
#pragma unroll
    for (int t = 0; t < 16; t++)
#pragma unroll
        for (int v = 0; v < 4; v++) acc[t][v] = 0.f;

    for (int chunk = 0; chunk < 16; chunk++) {
        const float4* xs = (const float4*)(Xg + (size_t)chunk * 64 * D);
#pragma unroll
        for (int q = 0; q < 8; q++) {
            int idx = tid + 256 * q;
            int row = idx >> 5, c4 = idx & 31;
            float4 f = xs[idx];
            uint32_t h01, l01, h23, l23;
            split2(f.x, f.y, h01, l01);
            split2(f.z, f.w, h23, l23);
            uint32_t off = (uint32_t)(row * GSROW + 4 * c4) * 2;
            *(uint2*)((char*)sXH + off) = make_uint2(h01, h23);
            *(uint2*)((char*)sXL + off) = make_uint2(l01, l23);
        }
        __syncthreads();

#pragma unroll
        for (int j = 0; j < 4; j++) {
            uint32_t aoff = ((j * 16 + arl) * GSROW + acol) * 2;
            uint32_t ah[4], al[4];
            ldsm4t(ah, sbh + aoff);
            ldsm4t(al, sbl + aoff);
#pragma unroll
            for (int tp = 0; tp < 8; tp++) {
                uint32_t boff = ((j * 16 + brl) * GSROW + (2 * tp + bct) * 8) * 2;
                uint32_t bh[4];
                ldsm4t(bh, sbh + boff);
                mma16816(acc[2 * tp],     ah, bh);
                mma16816(acc[2 * tp],     al, bh);
                mma16816(acc[2 * tp + 1], ah, bh + 2);
                mma16816(acc[2 * tp + 1], al, bh + 2);
            }
        }
        __syncthreads();
    }

    float* G = g_grams + ((size_t)split * NGRAPH + graph) * D * D;
    const int ra = lane >> 2;
    const int ca = (lane & 3) * 2;
#pragma unroll
    for (int t = 0; t < 16; t++) {
        int col = t * 8 + ca;
        *(float2*)&G[(m0 + ra) * D + col]     = make_float2(acc[t][0], acc[t][1]);
        *(float2*)&G[(m0 + ra + 8) * D + col] = make_float2(acc[t][2], acc[t][3]);
    }
}

// ---------------------------------------------------------------------------
// HMMA fused match kernel (fp16): 32 rows/block, 256 threads (8 warps),
// 2 blocks/SM. Warp w: mt = w>>2 (m16 tile), nq = w&3 (32-col quarter).
// Products done in FRAGMENT layout: the warp's product cols (nq*32..+31) are
// exactly X k-chunks j=2nq..2nq+1, and the C-fragment lane layout of accY
// equals the ldsm/stsm A-fragment layout -> products = 2x ldsm4 (x hi/lo) +
// register math + 4x stmatrix per chunk. No scalar smem ops.
// ---------------------------------------------------------------------------
#define SROW    136
#define OFF_XH  0u          //  8704 B  -> PN hi after products (stsm in place)
#define OFF_XL  8704u       //  8704 B  -> PN lo after products
#define OFF_BH  17408u      // 34816 B  (G hi, then W hi)
#define OFF_BL  52224u      // 34816 B  (G lo, then W lo)
#define OFF_P1H 87040u      //  8704 B
#define OFF_P2H 95744u      //  8704 B
#define SMEM_NEED 104448

__global__ __launch_bounds__(256, 2) void match_mma_kernel(
    const float* __restrict__ feats, float* __restrict__ out) {
    extern __shared__ __align__(16) char smem[];
    const uint32_t sb = smem_to_u32(smem);

    const int tid  = threadIdx.x;
    const int w    = tid >> 5;
    const int lane = tid & 31;
    const int mt   = w >> 2;       // m16 tile 0..1
    const int nq   = w & 3;        // n quarter (32 cols)
    const int r0   = blockIdx.x * 32;
    const int gi   = r0 >> 11;

    const uint2* ghp = (const uint2*)(g_gh + (size_t)(gi ^ 1) * D * D);
    const uint2* glp = (const uint2*)(g_gl + (size_t)(gi ^ 1) * D * D);
    const uint2* whp = (const uint2*)g_wh;
    const uint2* wlp = (const uint2*)g_wl;

    // ---- stage X (split hi/lo): 1024 float4, 4 per thread ----
    {
        const float4* xs = (const float4*)(feats + (size_t)r0 * D);
#pragma unroll
        for (int q = 0; q < 4; q++) {
            int idx = tid + 256 * q;
            int row = idx >> 5, c4 = idx & 31;
            float4 f = xs[idx];
            uint32_t h01, l01, h23, l23;
            split2(f.x, f.y, h01, l01);
            split2(f.z, f.w, h23, l23);
            uint32_t off = (uint32_t)(row * SROW + 4 * c4) * 2;
            *(uint2*)(smem + OFF_XH + off) = make_uint2(h01, h23);
            *(uint2*)(smem + OFF_XL + off) = make_uint2(l01, l23);
        }
    }
    // ---- stage G hi/lo: 4096 uint2 per buffer, 16 per thread ----
#pragma unroll
    for (int q = 0; q < 16; q++) {
        int pi = tid + 256 * q;
        int row = pi >> 5, cp2 = pi & 31;
        uint32_t off = (uint32_t)(row * SROW + 4 * cp2) * 2;
        *(uint2*)(smem + OFF_BH + off) = ghp[pi];
        *(uint2*)(smem + OFF_BL + off) = glp[pi];
    }
    __syncthreads();

    // fragment lane offsets
    const uint32_t arow = mt * 16 + (lane & 7) + ((lane >> 3) & 1) * 8;
    const uint32_t acolh = (lane >> 4) * 8;
    const int g    = lane >> 3;
    const uint32_t bnrow = (uint32_t)((g >> 1) * 8 + (lane & 7));
    const uint32_t bkoff = (uint32_t)((g & 1) * 8);

    // ---------------- Phase 1: Y = X * G (3-pass) ----------------
    float accY[4][4];
#pragma unroll
    for (int t = 0; t < 4; t++)
#pragma unroll
        for (int v = 0; v < 4; v++) accY[t][v] = 0.f;

#pragma unroll
    for (int j = 0; j < 8; j++) {
        uint32_t aoff = (arow * SROW + j * 16 + acolh) * 2;
        uint32_t ah[4], al[4];
        ldsm4(ah, sb + OFF_XH + aoff);
        ldsm4(al, sb + OFF_XL + aoff);
#pragma unroll
        for (int tp = 0; tp < 2; tp++) {
            uint32_t boff = (((uint32_t)(nq * 32 + tp * 16) + bnrow) * SROW + j * 16 + bkoff) * 2;
            uint32_t bh[4], bl2[4];
            ldsm4(bh,  sb + OFF_BH + boff);
            ldsm4(bl2, sb + OFF_BL + boff);
            mma16816(accY[2 * tp], ah, bh);
            mma16816(accY[2 * tp], al, bh);
            mma16816(accY[2 * tp], ah, bl2);
            mma16816(accY[2 * tp + 1], ah, bh + 2);
            mma16816(accY[2 * tp + 1], al, bh + 2);
            mma16816(accY[2 * tp + 1], ah, bl2 + 2);
        }
    }
    __syncthreads();   // all warps done reading G and X fragments

    // ---- stage W hi/lo (over G) ----
#pragma unroll
    for (int q = 0; q < 16; q++) {
        int pi = tid + 256 * q;
        int row = pi >> 5, cp2 = pi & 31;
        uint32_t off = (uint32_t)(row * SROW + 4 * cp2) * 2;
        *(uint2*)(smem + OFF_BH + off) = whp[pi];
        *(uint2*)(smem + OFF_BL + off) = wlp[pi];
    }

    // ---- products in fragment layout: warp's cols = X k-chunks 2nq, 2nq+1 ----
    // ldsm reg q: q0=(r,ca), q1=(r+8,ca), q2=(r,ca+8), q3=(r+8,ca+8)
    // accY[t][0..3] = (r,cc),(r,cc+1),(r+8,cc),(r+8,cc+1), cc = nq*32+t*8+ca
#pragma unroll
    for (int c2 = 0; c2 < 2; c2++) {
        int j = 2 * nq + c2;
        uint32_t aoff = (arow * SROW + j * 16 + acolh) * 2;
        uint32_t xh4[4], xl4[4];
        ldsm4(xh4, sb + OFF_XH + aoff);
        ldsm4(xl4, sb + OFF_XL + aoff);

        uint32_t pnh[4], pnl[4], p1h[4], p2h[4];
#pragma unroll
        for (int q = 0; q < 4; q++) {
            int t  = 2 * c2 + (q >> 1);       // n8 tile
            int rv = (q & 1) * 2;             // 0: rows r, 2: rows r+8
            float2 xhf = __half22float2(*(__half2*)&xh4[q]);
            float2 xlf = __half22float2(*(__half2*)&xl4[q]);
            float x0 = xhf.x + xlf.x;
            float x1 = xhf.y + xlf.y;
            float y0 = accY[t][rv]     * YSCALE;
            float y1 = accY[t][rv + 1] * YSCALE;
            split2(x0 * y0, x1 * y1, pnh[q], pnl[q]);
            p1h[q] = h2u(__floats2half2_rn(x0 * x0, x1 * x1));
            p2h[q] = h2u(__floats2half2_rn(y0 * y0, y1 * y1));
        }
        stsm4(sb + OFF_XH + aoff, pnh);    // PN hi in place over X hi
        stsm4(sb + OFF_XL + aoff, pnl);    // PN lo in place over X lo
        stsm4(sb + OFF_P1H + aoff, p1h);
        stsm4(sb + OFF_P2H + aoff, p2h);
    }
    __syncthreads();

    // ---------------- Phase 2 (merged): num 3-pass, n1 1-pass, n2 1-pass ----
    float accN[4][4], accB[4][4], accC[4][4];
#pragma unroll
    for (int t = 0; t < 4; t++)
#pragma unroll
        for (int v = 0; v < 4; v++) { accN[t][v] = 0.f; accB[t][v] = 0.f; accC[t][v] = 0.f; }

#pragma unroll
    for (int j = 0; j < 8; j++) {
        uint32_t aoff = (arow * SROW + j * 16 + acolh) * 2;
        uint32_t n_h[4], n_l[4], p1[4], p2[4];
        ldsm4(n_h, sb + OFF_XH + aoff);
        ldsm4(n_l, sb + OFF_XL + aoff);
        ldsm4(p1,  sb + OFF_P1H + aoff);
        ldsm4(p2,  sb + OFF_P2H + aoff);
#pragma unroll
        for (int tp = 0; tp < 2; tp++) {
            uint32_t boff = (((uint32_t)(nq * 32 + tp * 16) + bnrow) * SROW + j * 16 + bkoff) * 2;
            uint32_t wh_[4], wl_[4];
            ldsm4(wh_, sb + OFF_BH + boff);
            ldsm4(wl_, sb + OFF_BL + boff);
            mma16816(accN[2 * tp], n_h, wh_);
            mma16816(accN[2 * tp], n_l, wh_);
            mma16816(accN[2 * tp], n_h, wl_);
            mma16816(accB[2 * tp], p1, wh_);
            mma16816(accC[2 * tp], p2, wh_);
            mma16816(accN[2 * tp + 1], n_h, wh_ + 2);
            mma16816(accN[2 * tp + 1], n_l, wh_ + 2);
            mma16816(accN[2 * tp + 1], n_h, wl_ + 2);
            mma16816(accB[2 * tp + 1], p1, wh_ + 2);
            mma16816(accC[2 * tp + 1], p2, wh_ + 2);
        }
    }

    // ---------------- Epilogue ----------------
    const int ra = lane >> 2;
    const int ca = (lane & 3) * 2;
#pragma unroll
    for (int t = 0; t < 4; t++) {
        int col = nq * 32 + t * 8 + ca;
#pragma unroll
        for (int h2 = 0; h2 < 2; h2++) {
            int row = r0 + mt * 16 + ra + 8 * h2;
            float n0v = accN[t][2 * h2], n1v = accN[t][2 * h2 + 1];
            float b0v = accB[t][2 * h2], b1v = accB[t][2 * h2 + 1];
            float c0v = accC[t][2 * h2], c1v = accC[t][2 * h2 + 1];
            float2 o;
            o.x = n0v / fmaxf(sqrtf(b0v * c0v), EPS);
            o.y = n1v / fmaxf(sqrtf(b1v * c1v), EPS);
            *(float2*)(out + (size_t)row * D + col) = o;
        }
    }
}

// ---------------------------------------------------------------------------
extern "C" void kernel_launch(void* const* d_in, const int* in_sizes, int n_in,
                              void* d_out, int out_size) {
    const float* feats = (const float*)d_in[0];
    const float* mp_w  = (const float*)d_in[1];
    float* out = (float*)d_out;

    static bool attr_done = false;
    if (!attr_done) {
        cudaFuncSetAttribute(match_mma_kernel,
                             cudaFuncAttributeMaxDynamicSharedMemorySize, SMEM_NEED);
        attr_done = true;
    }

    int N = in_sizes[0] / D;   // 131072 rows

    wcvt_kernel<<<(D * D + 255) / 256, 256>>>(mp_w);
    gram_mma_kernel<<<NGRAPH * 2, 256>>>(feats);
    gram_cvt_kernel<<<(NGRAPH * D * D / 4 + 255) / 256, 256>>>();
    match_mma_kernel<<<N / 32, 256, SMEM_NEED>>>(feats, out);
}

// round 11
// speedup vs baseline: 5.3078x; 1.2995x over previous
#include <cuda_runtime.h>
#include <cuda_fp16.h>
#include <math.h>
#include <stdint.h>

#define D      128
#define NGRAPH 64
#define LROWS  2048
#define EPS    1e-8f
#define YSCALE 0.015625f   // 2^-6, exact

// ---------------------------------------------------------------------------
// Global scratch (hi-only B operands: G and W rounded to fp16, used
// consistently across num/n1/n2 -> exact cosine in rounded weights)
// ---------------------------------------------------------------------------
__device__ float  g_grams[2 * NGRAPH * D * D];   // two split-K partials
__device__ __half g_gh[NGRAPH * D * D];
__device__ __half g_wh[D * D];

// ---------------------------------------------------------------------------
// Helpers
// ---------------------------------------------------------------------------
__device__ __forceinline__ uint32_t smem_to_u32(const void* p) {
    uint32_t a;
    asm("{ .reg .u64 t; cvta.to.shared.u64 t, %1; cvt.u32.u64 %0, t; }" : "=r"(a) : "l"(p));
    return a;
}
__device__ __forceinline__ uint32_t h2u(__half2 h) { return *(uint32_t*)&h; }

__device__ __forceinline__ void ldsm4(uint32_t* r, uint32_t addr) {
    asm volatile("ldmatrix.sync.aligned.m8n8.x4.shared.b16 {%0,%1,%2,%3}, [%4];"
        : "=r"(r[0]), "=r"(r[1]), "=r"(r[2]), "=r"(r[3]) : "r"(addr));
}
__device__ __forceinline__ void ldsm4t(uint32_t* r, uint32_t addr) {
    asm volatile("ldmatrix.sync.aligned.m8n8.x4.trans.shared.b16 {%0,%1,%2,%3}, [%4];"
        : "=r"(r[0]), "=r"(r[1]), "=r"(r[2]), "=r"(r[3]) : "r"(addr));
}
__device__ __forceinline__ void stsm4(uint32_t addr, const uint32_t* r) {
    asm volatile("stmatrix.sync.aligned.m8n8.x4.shared.b16 [%0], {%1,%2,%3,%4};"
        :: "r"(addr), "r"(r[0]), "r"(r[1]), "r"(r[2]), "r"(r[3]) : "memory");
}
__device__ __forceinline__ void mma16816(float* c, const uint32_t* a, const uint32_t* b) {
    asm volatile("mma.sync.aligned.m16n8k16.row.col.f32.f16.f16.f32 "
        "{%0,%1,%2,%3}, {%4,%5,%6,%7}, {%8,%9}, {%0,%1,%2,%3};"
        : "+f"(c[0]), "+f"(c[1]), "+f"(c[2]), "+f"(c[3])
        : "r"(a[0]), "r"(a[1]), "r"(a[2]), "r"(a[3]), "r"(b[0]), "r"(b[1]));
}

// split a,b -> (hi half2, lo half2)
__device__ __forceinline__ void split2(float a, float b, uint32_t& hi, uint32_t& lo) {
    __half2 h = __floats2half2_rn(a, b);
    float2 hf = __half22float2(h);
    __half2 l = __floats2half2_rn(a - hf.x, b - hf.y);
    hi = h2u(h); lo = h2u(l);
}

// ---------------------------------------------------------------------------
__global__ void wcvt_kernel(const float* __restrict__ mp_w) {
    int idx = blockIdx.x * blockDim.x + threadIdx.x;
    if (idx >= D * D) return;
    float v = mp_w[idx];
    g_wh[idx] = __float2half_rn(v * v);
}

__global__ void gram_cvt_kernel() {
    int idx = blockIdx.x * blockDim.x + threadIdx.x;
    if (idx >= NGRAPH * D * D / 4) return;
    float4 a = *(const float4*)(g_grams + 4 * (size_t)idx);
    float4 b = *(const float4*)(g_grams + NGRAPH * D * D + 4 * (size_t)idx);
    __half2 h01 = __floats2half2_rn(a.x + b.x, a.y + b.y);
    __half2 h23 = __floats2half2_rn(a.z + b.z, a.w + b.w);
    *(uint2*)(g_gh + 4 * (size_t)idx) = make_uint2(h2u(h01), h2u(h23));
}

// ---------------------------------------------------------------------------
// HMMA Gram kernel (fp16, 2-pass on A-side): G[g] = X_g^T X_g.
// 128 blocks, K=1024 each.
// ---------------------------------------------------------------------------
#define GSROW 136

__global__ __launch_bounds__(256) void gram_mma_kernel(const float* __restrict__ feats) {
    __shared__ __half sXH[64 * GSROW];
    __shared__ __half sXL[64 * GSROW];
    const uint32_t sbh = smem_to_u32(sXH);
    const uint32_t sbl = smem_to_u32(sXL);

    const int tid  = threadIdx.x;
    const int w    = tid >> 5;
    const int lane = tid & 31;
    const int graph = blockIdx.x >> 1;
    const int split = blockIdx.x & 1;
    const int m0   = w * 16;

    const float* Xg = feats + ((size_t)graph * LROWS + (size_t)split * 1024) * D;

    const int g   = lane >> 3;
    const int li  = lane & 7;
    const uint32_t arl  = (uint32_t)((g >> 1) * 8 + li);
    const uint32_t acol = (uint32_t)(m0 + (g & 1) * 8);
    const uint32_t brl  = (uint32_t)((g & 1) * 8 + li);
    const uint32_t bct  = (uint32_t)(g >> 1);

    float acc[16][4];
#pragma unroll
    for (int t = 0; t < 16; t++)
#pragma unroll
        for (int v = 0; v < 4; v++) acc[t][v] = 0.f;

    for (int chunk = 0; chunk < 16; chunk++) {
        const float4* xs = (const float4*)(Xg + (size_t)chunk * 64 * D);
#pragma unroll
        for (int q = 0; q < 8; q++) {
            int idx = tid + 256 * q;
            int row = idx >> 5, c4 = idx & 31;
            float4 f = xs[idx];
            uint32_t h01, l01, h23, l23;
            split2(f.x, f.y, h01, l01);
            split2(f.z, f.w, h23, l23);
            uint32_t off = (uint32_t)(row * GSROW + 4 * c4) * 2;
            *(uint2*)((char*)sXH + off) = make_uint2(h01, h23);
            *(uint2*)((char*)sXL + off) = make_uint2(l01, l23);
        }
        __syncthreads();

#pragma unroll
        for (int j = 0; j < 4; j++) {
            uint32_t aoff = ((j * 16 + arl) * GSROW + acol) * 2;
            uint32_t ah[4], al[4];
            ldsm4t(ah, sbh + aoff);
            ldsm4t(al, sbl + aoff);
#pragma unroll
            for (int tp = 0; tp < 8; tp++) {
                uint32_t boff = ((j * 16 + brl) * GSROW + (2 * tp + bct) * 8) * 2;
                uint32_t bh[4];
                ldsm4t(bh, sbh + boff);
                mma16816(acc[2 * tp],     ah, bh);
                mma16816(acc[2 * tp],     al, bh);
                mma16816(acc[2 * tp + 1], ah, bh + 2);
                mma16816(acc[2 * tp + 1], al, bh + 2);
            }
        }
        __syncthreads();
    }

    float* G = g_grams + ((size_t)split * NGRAPH + graph) * D * D;
    const int ra = lane >> 2;
    const int ca = (lane & 3) * 2;
#pragma unroll
    for (int t = 0; t < 16; t++) {
        int col = t * 8 + ca;
        *(float2*)&G[(m0 + ra) * D + col]     = make_float2(acc[t][0], acc[t][1]);
        *(float2*)&G[(m0 + ra + 8) * D + col] = make_float2(acc[t][2], acc[t][3]);
    }
}

// ---------------------------------------------------------------------------
// HMMA fused match kernel (fp16): 32 rows/block, 256 threads (8 warps),
// 2 blocks/SM. B operands hi-only (G, W rounded to fp16, used consistently).
// Phase1: Y = X*Gh (2-pass: Xh+Xl). Products in fragment layout (ldsm/stsm).
// Phase2: num = PN*Wh (2-pass), n1 = P1h*Wh, n2 = P2h*Wh (1-pass each).
// smem 68KB -> 2 blocks/SM.
// ---------------------------------------------------------------------------
#define SROW    136
#define OFF_XH  0u          //  8704 B  -> PN hi after products (stsm in place)
#define OFF_XL  8704u       //  8704 B  -> PN lo after products
#define OFF_BH  17408u      // 34816 B  (G hi, then W hi)
#define OFF_P1H 52224u      //  8704 B
#define OFF_P2H 60928u      //  8704 B
#define SMEM_NEED 69632

__global__ __launch_bounds__(256, 2) void match_mma_kernel(
    const float* __restrict__ feats, float* __restrict__ out) {
    extern __shared__ __align__(16) char smem[];
    const uint32_t sb = smem_to_u32(smem);

    const int tid  = threadIdx.x;
    const int w    = tid >> 5;
    const int lane = tid & 31;
    const int mt   = w >> 2;       // m16 tile 0..1
    const int nq   = w & 3;        // n quarter (32 cols)
    const int r0   = blockIdx.x * 32;
    const int gi   = r0 >> 11;

    const uint2* ghp = (const uint2*)(g_gh + (size_t)(gi ^ 1) * D * D);
    const uint2* whp = (const uint2*)g_wh;

    // ---- stage X (split hi/lo): 1024 float4, 4 per thread ----
    {
        const float4* xs = (const float4*)(feats + (size_t)r0 * D);
#pragma unroll
        for (int q = 0; q < 4; q++) {
            int idx = tid + 256 * q;
            int row = idx >> 5, c4 = idx & 31;
            float4 f = xs[idx];
            uint32_t h01, l01, h23, l23;
            split2(f.x, f.y, h01, l01);
            split2(f.z, f.w, h23, l23);
            uint32_t off = (uint32_t)(row * SROW + 4 * c4) * 2;
            *(uint2*)(smem + OFF_XH + off) = make_uint2(h01, h23);
            *(uint2*)(smem + OFF_XL + off) = make_uint2(l01, l23);
        }
    }
    // ---- stage G hi: 4096 uint2, 16 per thread ----
#pragma unroll
    for (int q = 0; q < 16; q++) {
        int pi = tid + 256 * q;
        int row = pi >> 5, cp2 = pi & 31;
        uint32_t off = (uint32_t)(row * SROW + 4 * cp2) * 2;
        *(uint2*)(smem + OFF_BH + off) = ghp[pi];
    }
    __syncthreads();

    // fragment lane offsets
    const uint32_t arow = mt * 16 + (lane & 7) + ((lane >> 3) & 1) * 8;
    const uint32_t acolh = (lane >> 4) * 8;
    const int g    = lane >> 3;
    const uint32_t bnrow = (uint32_t)((g >> 1) * 8 + (lane & 7));
    const uint32_t bkoff = (uint32_t)((g & 1) * 8);

    // ---------------- Phase 1: Y = X * Gh (2-pass) ----------------
    float accY[4][4];
#pragma unroll
    for (int t = 0; t < 4; t++)
#pragma unroll
        for (int v = 0; v < 4; v++) accY[t][v] = 0.f;

#pragma unroll
    for (int j = 0; j < 8; j++) {
        uint32_t aoff = (arow * SROW + j * 16 + acolh) * 2;
        uint32_t ah[4], al[4];
        ldsm4(ah, sb + OFF_XH + aoff);
        ldsm4(al, sb + OFF_XL + aoff);
#pragma unroll
        for (int tp = 0; tp < 2; tp++) {
            uint32_t boff = (((uint32_t)(nq * 32 + tp * 16) + bnrow) * SROW + j * 16 + bkoff) * 2;
            uint32_t bh[4];
            ldsm4(bh, sb + OFF_BH + boff);
            mma16816(accY[2 * tp], ah, bh);
            mma16816(accY[2 * tp], al, bh);
            mma16816(accY[2 * tp + 1], ah, bh + 2);
            mma16816(accY[2 * tp + 1], al, bh + 2);
        }
    }
    __syncthreads();   // all warps done reading G and X fragments

    // ---- stage W hi (over G) ----
#pragma unroll
    for (int q = 0; q < 16; q++) {
        int pi = tid + 256 * q;
        int row = pi >> 5, cp2 = pi & 31;
        uint32_t off = (uint32_t)(row * SROW + 4 * cp2) * 2;
        *(uint2*)(smem + OFF_BH + off) = whp[pi];
    }

    // ---- products in fragment layout: warp's cols = X k-chunks 2nq, 2nq+1 ----
#pragma unroll
    for (int c2 = 0; c2 < 2; c2++) {
        int j = 2 * nq + c2;
        uint32_t aoff = (arow * SROW + j * 16 + acolh) * 2;
        uint32_t xh4[4], xl4[4];
        ldsm4(xh4, sb + OFF_XH + aoff);
        ldsm4(xl4, sb + OFF_XL + aoff);

        uint32_t pnh[4], pnl[4], p1h[4], p2h[4];
#pragma unroll
        for (int q = 0; q < 4; q++) {
            int t  = 2 * c2 + (q >> 1);       // n8 tile
            int rv = (q & 1) * 2;             // 0: rows r, 2: rows r+8
            float2 xhf = __half22float2(*(__half2*)&xh4[q]);
            float2 xlf = __half22float2(*(__half2*)&xl4[q]);
            float x0 = xhf.x + xlf.x;
            float x1 = xhf.y + xlf.y;
            float y0 = accY[t][rv]     * YSCALE;
            float y1 = accY[t][rv + 1] * YSCALE;
            split2(x0 * y0, x1 * y1, pnh[q], pnl[q]);
            p1h[q] = h2u(__floats2half2_rn(x0 * x0, x1 * x1));
            p2h[q] = h2u(__floats2half2_rn(y0 * y0, y1 * y1));
        }
        stsm4(sb + OFF_XH + aoff, pnh);    // PN hi in place over X hi
        stsm4(sb + OFF_XL + aoff, pnl);    // PN lo in place over X lo
        stsm4(sb + OFF_P1H + aoff, p1h);
        stsm4(sb + OFF_P2H + aoff, p2h);
    }
    __syncthreads();

    // ---------------- Phase 2: num 2-pass, n1 1-pass, n2 1-pass ----------
    float accN[4][4], accB[4][4], accC[4][4];
#pragma unroll
    for (int t = 0; t < 4; t++)
#pragma unroll
        for (int v = 0; v < 4; v++) { accN[t][v] = 0.f; accB[t][v] = 0.f; accC[t][v] = 0.f; }

#pragma unroll
    for (int j = 0; j < 8; j++) {
        uint32_t aoff = (arow * SROW + j * 16 + acolh) * 2;
        uint32_t n_h[4], n_l[4], p1[4], p2[4];
        ldsm4(n_h, sb + OFF_XH + aoff);
        ldsm4(n_l, sb + OFF_XL + aoff);
        ldsm4(p1,  sb + OFF_P1H + aoff);
        ldsm4(p2,  sb + OFF_P2H + aoff);
#pragma unroll
        for (int tp = 0; tp < 2; tp++) {
            uint32_t boff = (((uint32_t)(nq * 32 + tp * 16) + bnrow) * SROW + j * 16 + bkoff) * 2;
            uint32_t wh_[4];
            ldsm4(wh_, sb + OFF_BH + boff);
            mma16816(accN[2 * tp], n_h, wh_);
            mma16816(accN[2 * tp], n_l, wh_);
            mma16816(accB[2 * tp], p1, wh_);
            mma16816(accC[2 * tp], p2, wh_);
            mma16816(accN[2 * tp + 1], n_h, wh_ + 2);
            mma16816(accN[2 * tp + 1], n_l, wh_ + 2);
            mma16816(accB[2 * tp + 1], p1, wh_ + 2);
            mma16816(accC[2 * tp + 1], p2, wh_ + 2);
        }
    }

    // ---------------- Epilogue ----------------
    const int ra = lane >> 2;
    const int ca = (lane & 3) * 2;
#pragma unroll
    for (int t = 0; t < 4; t++) {
        int col = nq * 32 + t * 8 + ca;
#pragma unroll
        for (int h2 = 0; h2 < 2; h2++) {
            int row = r0 + mt * 16 + ra + 8 * h2;
            float n0v = accN[t][2 * h2], n1v = accN[t][2 * h2 + 1];
            float b0v = accB[t][2 * h2], b1v = accB[t][2 * h2 + 1];
            float c0v = accC[t][2 * h2], c1v = accC[t][2 * h2 + 1];
            float2 o;
            o.x = n0v / fmaxf(sqrtf(b0v * c0v), EPS);
            o.y = n1v / fmaxf(sqrtf(b1v * c1v), EPS);
            *(float2*)(out + (size_t)row * D + col) = o;
        }
    }
}

// ---------------------------------------------------------------------------
extern "C" void kernel_launch(void* const* d_in, const int* in_sizes, int n_in,
                              void* d_out, int out_size) {
    const float* feats = (const float*)d_in[0];
    const float* mp_w  = (const float*)d_in[1];
    float* out = (float*)d_out;

    static bool attr_done = false;
    if (!attr_done) {
        cudaFuncSetAttribute(match_mma_kernel,
                             cudaFuncAttributeMaxDynamicSharedMemorySize, SMEM_NEED);
        attr_done = true;
    }

    int N = in_sizes[0] / D;   // 131072 rows

    wcvt_kernel<<<(D * D + 255) / 256, 256>>>(mp_w);
    gram_mma_kernel<<<NGRAPH * 2, 256>>>(feats);
    gram_cvt_kernel<<<(NGRAPH * D * D / 4 + 255) / 256, 256>>>();
    match_mma_kernel<<<N / 32, 256, SMEM_NEED>>>(feats, out);
}